// round 3
// baseline (speedup 1.0000x reference)
#include <cuda_runtime.h>
#include <cuda_bf16.h>
#include <math.h>

// Problem dims
#define BB   32
#define LL   1024
#define DD   512
#define HH   512
#define G4   2048
#define FF   256
#define OUTD 100
#define NCTA_LSTM 128
#define WIN  64          // exact softmax window; beyond this exp(score*decay - m) == exp(-m) in fp32

// ---------------- scratch (device globals; no allocation) ----------------
__device__ float g_pre  [BB * LL * G4];     // 256 MB  gates pre-activation (x part + cpart)
__device__ float g_cpart[BB * G4];          // concept part + biases
__device__ float g_hout [BB * LL * HH];     // LSTM hidden states
__device__ float g_hbuf [2 * HH * BB];      // transposed h double buffer [buf][k][b]
__device__ float g_mlp  [BB * LL * DD];     // mlp_out
__device__ float g_P    [BB * LL * HH];     // cumsum of hout over t
__device__ float g_wgt  [BB * LL * HH];     // attention output
__device__ float g_h1   [BB * LL * FF];     // relu(W1 ...)
__device__ unsigned g_ctr;
__device__ unsigned g_gen;

// ---------------- init: zero h buffers + barrier state ----------------
__global__ void k_init() {
    int i = blockIdx.x * 256 + threadIdx.x;
    if (i < 2 * HH * BB) g_hbuf[i] = 0.0f;
    if (i == 0) { g_ctr = 0u; g_gen = 0u; }
}

// ---------------- cpart[b][g] = emb[concepts[b]] . Wih[g][512:1024] + bih[g] + bhh[g] --------
__global__ void k_cpart(const float* __restrict__ emb, const int* __restrict__ concepts,
                        const float* __restrict__ Wih, const float* __restrict__ bih,
                        const float* __restrict__ bhh) {
    int b = blockIdx.x >> 3;
    int g = ((blockIdx.x & 7) << 8) + threadIdx.x;   // 8 chunks * 256
    const float4* e  = (const float4*)(emb + (long)concepts[b] * HH);
    const float4* w  = (const float4*)(Wih + (long)g * (2 * DD) + DD);
    float acc = bih[g] + bhh[g];
#pragma unroll 4
    for (int k = 0; k < HH / 4; k++) {
        float4 wv = __ldg(w + k);
        float4 ev = __ldg(e + k);
        acc += wv.x * ev.x + wv.y * ev.y + wv.z * ev.z + wv.w * ev.w;
    }
    g_cpart[b * G4 + g] = acc;
}

// ---------------- generic SGEMM: C[M,N] = A[M,K] * W[N,:K]^T (+bias[n]) (+rowvec[(m>>10)*N+n]) --
// BM=128, BN=64, BK=16, 256 threads, 8x4 register tile. M must be a multiple of 128, K of 16.
template<bool RELU>
__global__ void k_gemm(const float* __restrict__ A, int lda,
                       const float* __restrict__ W, int ldw,
                       const float* __restrict__ bias,
                       const float* __restrict__ rowvec,
                       float* __restrict__ C, int ldc,
                       int N, int K) {
    __shared__ float As[16 * 132];
    __shared__ float Bs[16 * 68];
    int tid = threadIdx.x;
    int bx = blockIdx.x, by = blockIdx.y;
    int tx = tid & 15, ty = tid >> 4;

    float acc[8][4];
#pragma unroll
    for (int i = 0; i < 8; i++)
#pragma unroll
        for (int j = 0; j < 4; j++) acc[i][j] = 0.0f;

    int ml = tid >> 2;              // 0..63
    int kl = (tid & 3) * 4;         // 0,4,8,12
    const float* Abase = A + (long)(by * 128 + ml) * lda + kl;
    int n_load = bx * 64 + ml;      // row of W this thread loads
    const float* Wbase = (n_load < N) ? (W + (long)n_load * ldw + kl) : nullptr;

    for (int kt = 0; kt < K; kt += 16) {
        float4 a0 = *(const float4*)(Abase + kt);
        float4 a1 = *(const float4*)(Abase + kt + (long)64 * lda);
        float4 b0 = make_float4(0.f, 0.f, 0.f, 0.f);
        if (Wbase) b0 = *(const float4*)(Wbase + kt);
        As[(kl + 0) * 132 + ml]      = a0.x;
        As[(kl + 1) * 132 + ml]      = a0.y;
        As[(kl + 2) * 132 + ml]      = a0.z;
        As[(kl + 3) * 132 + ml]      = a0.w;
        As[(kl + 0) * 132 + ml + 64] = a1.x;
        As[(kl + 1) * 132 + ml + 64] = a1.y;
        As[(kl + 2) * 132 + ml + 64] = a1.z;
        As[(kl + 3) * 132 + ml + 64] = a1.w;
        Bs[(kl + 0) * 68 + ml] = b0.x;
        Bs[(kl + 1) * 68 + ml] = b0.y;
        Bs[(kl + 2) * 68 + ml] = b0.z;
        Bs[(kl + 3) * 68 + ml] = b0.w;
        __syncthreads();
#pragma unroll
        for (int k = 0; k < 16; k++) {
            float4 av0 = *(const float4*)&As[k * 132 + ty * 8];
            float4 av1 = *(const float4*)&As[k * 132 + ty * 8 + 4];
            float4 bv  = *(const float4*)&Bs[k * 68 + tx * 4];
            float a[8] = {av0.x, av0.y, av0.z, av0.w, av1.x, av1.y, av1.z, av1.w};
            float bvv[4] = {bv.x, bv.y, bv.z, bv.w};
#pragma unroll
            for (int i = 0; i < 8; i++)
#pragma unroll
                for (int j = 0; j < 4; j++) acc[i][j] += a[i] * bvv[j];
        }
        __syncthreads();
    }

    int m0 = by * 128 + ty * 8, n0 = bx * 64 + tx * 4;
#pragma unroll
    for (int i = 0; i < 8; i++) {
        int m = m0 + i;
        const float* rv = rowvec ? (rowvec + (long)(m >> 10) * N) : nullptr;
#pragma unroll
        for (int j = 0; j < 4; j++) {
            int n = n0 + j;
            if (n < N) {
                float v = acc[i][j];
                if (bias) v += bias[n];
                if (rv)   v += rv[n];
                if (RELU) v = fmaxf(v, 0.0f);
                C[(long)m * ldc + n] = v;
            }
        }
    }
}

// ---------------- persistent LSTM ----------------
// 128 CTAs x 256 threads. CTA owns hidden dims j0..j0+3 => 16 gate rows (i,f,g,o blocks).
// Per step: grid barrier -> stage full h (transposed) into smem -> gates -> activations -> publish h.
__global__ void k_lstm(const float* __restrict__ pre, const float* __restrict__ Whh) {
    extern __shared__ float sm[];
    float* w_s = sm;                      // [16][512]
    float* h_s = sm + 16 * 512;           // [512][36]
    float* g_s = h_s + 512 * 36;          // [16][33]
    float* c_s = g_s + 16 * 33;           // [128]
    float* hw  = c_s + 128;               // [32][4]

    int tid = threadIdx.x;
    int cta = blockIdx.x;
    int j0  = cta * 4;

    // load Whh slice: rows glob(lr) = (lr/4)*512 + j0 + (lr%4)
    for (int i = tid; i < 16 * 512; i += 256) {
        int lr = i >> 9, k = i & 511;
        int g  = ((lr >> 2) << 9) + j0 + (lr & 3);
        w_s[lr * 512 + k] = Whh[(long)g * HH + k];
    }
    if (tid < 128) c_s[tid] = 0.0f;
    __syncthreads();

    int lr = tid >> 4;        // 0..15 local gate row
    int bp = tid & 15;        // batch pair
    int grow = ((lr >> 2) << 9) + j0 + (lr & 3);   // global gate row

    for (int t = 0; t < LL; t++) {
        const float* hb  = g_hbuf + (t & 1) * HH * BB;        // read  [512][32]
        float*       hbn = g_hbuf + ((t + 1) & 1) * HH * BB;  // write

        // stage h -> smem transposed with pad 36 (ldcg: bypass stale L1)
        for (int i = tid; i < HH * BB / 4; i += 256) {
            float4 v = __ldcg((const float4*)hb + i);
            int i4 = i * 4;
            int k  = i4 >> 5;
            int b4 = i4 & 31;
            *(float4*)(h_s + k * 36 + b4) = v;
        }
        __syncthreads();

        // gates: 2 outputs per thread (same row, batches 2bp, 2bp+1)
        {
            long base = ((long)(2 * bp) * LL + t) * G4 + grow;
            float acc0 = __ldg(pre + base);
            float acc1 = __ldg(pre + base + (long)LL * G4);
            const float4* w4 = (const float4*)(w_s + lr * 512);
            const float* hs2 = h_s + 2 * bp;
#pragma unroll 8
            for (int kk = 0; kk < 128; kk++) {
                float4 wv = w4[kk];
                const float* hp = hs2 + (kk * 4) * 36;
                float2 h0 = *(const float2*)(hp);
                float2 h1 = *(const float2*)(hp + 36);
                float2 h2 = *(const float2*)(hp + 72);
                float2 h3 = *(const float2*)(hp + 108);
                acc0 += wv.x * h0.x; acc1 += wv.x * h0.y;
                acc0 += wv.y * h1.x; acc1 += wv.y * h1.y;
                acc0 += wv.z * h2.x; acc1 += wv.z * h2.y;
                acc0 += wv.w * h3.x; acc1 += wv.w * h3.y;
            }
            g_s[lr * 33 + 2 * bp]     = acc0;
            g_s[lr * 33 + 2 * bp + 1] = acc1;
        }
        __syncthreads();

        // activations + state update (128 threads, one (jl,b) each)
        if (tid < 128) {
            int jl = tid >> 5, b = tid & 31;
            float gi = g_s[(jl)      * 33 + b];
            float gf = g_s[(4 + jl)  * 33 + b];
            float gg = g_s[(8 + jl)  * 33 + b];
            float go = g_s[(12 + jl) * 33 + b];
            float si = 1.0f / (1.0f + __expf(-gi));
            float sf = 1.0f / (1.0f + __expf(-gf));
            float so = 1.0f / (1.0f + __expf(-go));
            float tg = tanhf(gg);
            float c  = sf * c_s[tid] + si * tg;
            c_s[tid] = c;
            float h  = so * tanhf(c);
            hbn[(j0 + jl) * BB + b] = h;      // transposed publish for next step
            hw[b * 4 + jl] = h;
        }
        __syncthreads();
        // coalesced hout write (float4 per batch row)
        if (tid < 32) {
            float4 v = *(const float4*)&hw[tid * 4];
            *(float4*)(g_hout + ((long)tid * LL + t) * HH + j0) = v;
        }
        __threadfence();
        __syncthreads();
        if (tid == 0) {
            unsigned a = atomicAdd(&g_ctr, 1u);
            if (a == (unsigned)t * NCTA_LSTM + (NCTA_LSTM - 1)) {
                __threadfence();
                atomicExch(&g_gen, (unsigned)(t + 1));
            } else {
                while (*((volatile unsigned*)&g_gen) < (unsigned)(t + 1)) __nanosleep(64);
            }
        }
        __syncthreads();
    }
}

// ---------------- cumsum over time: P[b][t][d] = sum_{s<=t} hout[b][s][d] ----------------
__global__ void k_cumsum() {
    int b = blockIdx.x >> 1;
    int d = ((blockIdx.x & 1) << 8) + threadIdx.x;
    const float* src = g_hout + (long)b * LL * HH + d;
    float* dst = g_P + (long)b * LL * HH + d;
    float acc = 0.0f;
#pragma unroll 4
    for (int t = 0; t < LL; t++) {
        acc += src[(long)t * HH];
        dst[(long)t * HH] = acc;
    }
}

// ---------------- banded online-softmax attention ----------------
__device__ __forceinline__ void upd(float& m, float& l, float4* acc, float sc, const float4* ov) {
    if (sc <= m) {
        float e = __expf(sc - m);
        l += e;
#pragma unroll
        for (int j = 0; j < 4; j++) {
            acc[j].x += e * ov[j].x; acc[j].y += e * ov[j].y;
            acc[j].z += e * ov[j].z; acc[j].w += e * ov[j].w;
        }
    } else {
        float coef = __expf(m - sc);
        l = l * coef + 1.0f;
#pragma unroll
        for (int j = 0; j < 4; j++) {
            acc[j].x = acc[j].x * coef + ov[j].x; acc[j].y = acc[j].y * coef + ov[j].y;
            acc[j].z = acc[j].z * coef + ov[j].z; acc[j].w = acc[j].w * coef + ov[j].w;
        }
        m = sc;
    }
}

__global__ void k_attn() {
    int warp = (blockIdx.x * blockDim.x + threadIdx.x) >> 5;  // 0..16383
    int lane = threadIdx.x & 31;
    int b  = warp >> 9;
    int tp = warp & 511;
    int t0 = tp * 2, t1 = t0 + 1;

    const float* mb = g_mlp  + (long)b * LL * DD;
    const float* ob = g_hout + (long)b * LL * HH;

    float4 q0[4], q1[4], acc0[4], acc1[4];
#pragma unroll
    for (int j = 0; j < 4; j++) {
        q0[j] = *(const float4*)(mb + (long)t0 * DD + lane * 4 + j * 128);
        q1[j] = *(const float4*)(mb + (long)t1 * DD + lane * 4 + j * 128);
        acc0[j] = make_float4(0.f, 0.f, 0.f, 0.f);
        acc1[j] = make_float4(0.f, 0.f, 0.f, 0.f);
    }
    float m0 = -1e30f, m1 = -1e30f, l0 = 0.0f, l1 = 0.0f;

    int slo = t0 - (WIN - 1); if (slo < 0) slo = 0;
    for (int s = slo; s <= t1; s++) {
        float4 ov[4];
        const float* op = ob + (long)s * HH + lane * 4;
#pragma unroll
        for (int j = 0; j < 4; j++) ov[j] = *(const float4*)(op + j * 128);
        float d0 = 0.f, d1 = 0.f;
#pragma unroll
        for (int j = 0; j < 4; j++) {
            d0 += q0[j].x * ov[j].x + q0[j].y * ov[j].y + q0[j].z * ov[j].z + q0[j].w * ov[j].w;
            d1 += q1[j].x * ov[j].x + q1[j].y * ov[j].y + q1[j].z * ov[j].z + q1[j].w * ov[j].w;
        }
#pragma unroll
        for (int off = 16; off; off >>= 1) {
            d0 += __shfl_xor_sync(0xFFFFFFFFu, d0, off);
            d1 += __shfl_xor_sync(0xFFFFFFFFu, d1, off);
        }
        if (s <= t0) {
            float sc = d0 * __expf(-0.6f * (float)(t0 - s));
            upd(m0, l0, acc0, sc, ov);
        }
        if (s >= t1 - (WIN - 1)) {
            float sc = d1 * __expf(-0.6f * (float)(t1 - s));
            upd(m1, l1, acc1, sc, ov);
        }
    }
    // tails: all s <= t-WIN contribute exactly exp(-m) each (fp32-exact vs reference)
    if (t0 >= WIN) {
        float cnt = (float)(t0 - (WIN - 1));
        const float* pp = g_P + ((long)b * LL + (t0 - WIN)) * HH + lane * 4;
        float4 pv[4];
#pragma unroll
        for (int j = 0; j < 4; j++) pv[j] = *(const float4*)(pp + j * 128);
        if (0.0f <= m0) {
            float e = __expf(-m0);
            l0 += cnt * e;
#pragma unroll
            for (int j = 0; j < 4; j++) {
                acc0[j].x += e * pv[j].x; acc0[j].y += e * pv[j].y;
                acc0[j].z += e * pv[j].z; acc0[j].w += e * pv[j].w;
            }
        } else {
            float coef = __expf(m0);
            l0 = l0 * coef + cnt;
#pragma unroll
            for (int j = 0; j < 4; j++) {
                acc0[j].x = acc0[j].x * coef + pv[j].x; acc0[j].y = acc0[j].y * coef + pv[j].y;
                acc0[j].z = acc0[j].z * coef + pv[j].z; acc0[j].w = acc0[j].w * coef + pv[j].w;
            }
            m0 = 0.0f;
        }
    }
    if (t1 >= WIN) {
        float cnt = (float)(t1 - (WIN - 1));
        const float* pp = g_P + ((long)b * LL + (t1 - WIN)) * HH + lane * 4;
        float4 pv[4];
#pragma unroll
        for (int j = 0; j < 4; j++) pv[j] = *(const float4*)(pp + j * 128);
        if (0.0f <= m1) {
            float e = __expf(-m1);
            l1 += cnt * e;
#pragma unroll
            for (int j = 0; j < 4; j++) {
                acc1[j].x += e * pv[j].x; acc1[j].y += e * pv[j].y;
                acc1[j].z += e * pv[j].z; acc1[j].w += e * pv[j].w;
            }
        } else {
            float coef = __expf(m1);
            l1 = l1 * coef + cnt;
#pragma unroll
            for (int j = 0; j < 4; j++) {
                acc1[j].x = acc1[j].x * coef + pv[j].x; acc1[j].y = acc1[j].y * coef + pv[j].y;
                acc1[j].z = acc1[j].z * coef + pv[j].z; acc1[j].w = acc1[j].w * coef + pv[j].w;
            }
            m1 = 0.0f;
        }
    }

    float inv0 = 1.0f / l0, inv1 = 1.0f / l1;
    float* w0 = g_wgt + ((long)b * LL + t0) * HH + lane * 4;
    float* w1 = g_wgt + ((long)b * LL + t1) * HH + lane * 4;
#pragma unroll
    for (int j = 0; j < 4; j++) {
        float4 r0 = make_float4(acc0[j].x * inv0, acc0[j].y * inv0, acc0[j].z * inv0, acc0[j].w * inv0);
        float4 r1 = make_float4(acc1[j].x * inv1, acc1[j].y * inv1, acc1[j].z * inv1, acc1[j].w * inv1);
        *(float4*)(w0 + j * 128) = r0;
        *(float4*)(w1 + j * 128) = r1;
    }
}

// ---------------- launch ----------------
extern "C" void kernel_launch(void* const* d_in, const int* in_sizes, int n_in,
                              void* d_out, int out_size) {
    const float* x        = (const float*)d_in[0];
    const int*   concepts = (const int*)  d_in[1];
    const float* emb      = (const float*)d_in[2];
    const float* Wih      = (const float*)d_in[3];
    const float* Whh      = (const float*)d_in[4];
    const float* bih      = (const float*)d_in[5];
    const float* bhh      = (const float*)d_in[6];
    const float* Wm       = (const float*)d_in[7];
    const float* bm       = (const float*)d_in[8];
    const float* W1       = (const float*)d_in[9];
    const float* b1       = (const float*)d_in[10];
    const float* W2       = (const float*)d_in[11];
    const float* b2       = (const float*)d_in[12];
    float* out = (float*)d_out;

    float *p_pre, *p_cpart, *p_mlp, *p_wgt, *p_h1;
    cudaGetSymbolAddress((void**)&p_pre,   g_pre);
    cudaGetSymbolAddress((void**)&p_cpart, g_cpart);
    cudaGetSymbolAddress((void**)&p_mlp,   g_mlp);
    cudaGetSymbolAddress((void**)&p_wgt,   g_wgt);
    cudaGetSymbolAddress((void**)&p_h1,    g_h1);

    const int lstm_smem = (16 * 512 + 512 * 36 + 16 * 33 + 128 + 128) * 4;
    cudaFuncSetAttribute(k_lstm, cudaFuncAttributeMaxDynamicSharedMemorySize, lstm_smem);

    const int M = BB * LL;   // 32768

    k_init<<<128, 256>>>();
    k_cpart<<<BB * 8, 256>>>(emb, concepts, Wih, bih, bhh);
    // pre = x @ WihA^T + cpart   (WihA = first 512 cols of Wih, ldw = 1024)
    k_gemm<false><<<dim3(G4 / 64, M / 128), 256>>>(x, DD, Wih, 2 * DD, nullptr, p_cpart,
                                                   p_pre, G4, G4, DD);
    // mlp = x @ Wm^T + bm
    k_gemm<false><<<dim3(DD / 64, M / 128), 256>>>(x, DD, Wm, DD, bm, nullptr,
                                                   p_mlp, DD, DD, DD);
    // LSTM recurrence
    k_lstm<<<NCTA_LSTM, 256, lstm_smem>>>(p_pre, Whh);
    // prefix sums of h over time
    k_cumsum<<<BB * 2, 256>>>();
    // attention
    k_attn<<<2048, 256>>>();
    // h1 = relu(weighted @ W1^T + b1)
    k_gemm<true><<<dim3(FF / 64, M / 128), 256>>>(p_wgt, HH, W1, HH, b1, nullptr,
                                                  p_h1, FF, FF, HH);
    // res = h1 @ W2^T + b2
    k_gemm<false><<<dim3((OUTD + 63) / 64, M / 128), 256>>>(p_h1, FF, W2, FF, b2, nullptr,
                                                            out, OUTD, OUTD, FF);
}

// round 4
// speedup vs baseline: 1.3596x; 1.3596x over previous
#include <cuda_runtime.h>
#include <cuda_bf16.h>
#include <math.h>

// Problem dims
#define BB   32
#define LL   1024
#define DD   512
#define HH   512
#define G4   2048
#define FF   256
#define OUTD 100
#define NCTA_LSTM 128
#define WIN  64          // exact softmax window; beyond this exp(score*decay - m) == exp(-m) in fp32

// ---------------- scratch (device globals; no allocation) ----------------
__device__ float g_pre  [BB * LL * G4];     // gates pre-activation (x part + cpart)
__device__ float g_cpart[BB * G4];          // concept part + biases
__device__ float g_hout [BB * LL * HH];     // LSTM hidden states
__device__ float g_hbuf [2 * HH * BB];      // h double buffer [buf][k][b]
__device__ float g_mlp  [BB * LL * DD];     // mlp_out
__device__ float g_P    [BB * LL * HH];     // cumsum of hout over t
__device__ float g_wgt  [BB * LL * HH];     // attention output
__device__ float g_h1   [BB * LL * FF];     // relu(W1 ...)
__device__ unsigned g_ctr;
__device__ unsigned g_gen;

// ---------------- init: zero h buffers + barrier state ----------------
__global__ void k_init() {
    int i = blockIdx.x * 256 + threadIdx.x;
    if (i < 2 * HH * BB) g_hbuf[i] = 0.0f;
    if (i == 0) { g_ctr = 0u; g_gen = 0u; }
}

// ---------------- cpart[b][g] = emb[concepts[b]] . Wih[g][512:1024] + bih[g] + bhh[g] --------
__global__ void k_cpart(const float* __restrict__ emb, const int* __restrict__ concepts,
                        const float* __restrict__ Wih, const float* __restrict__ bih,
                        const float* __restrict__ bhh) {
    int b = blockIdx.x >> 3;
    int g = ((blockIdx.x & 7) << 8) + threadIdx.x;   // 8 chunks * 256
    const float4* e  = (const float4*)(emb + (long)concepts[b] * HH);
    const float4* w  = (const float4*)(Wih + (long)g * (2 * DD) + DD);
    float acc = bih[g] + bhh[g];
#pragma unroll 4
    for (int k = 0; k < HH / 4; k++) {
        float4 wv = __ldg(w + k);
        float4 ev = __ldg(e + k);
        acc += wv.x * ev.x + wv.y * ev.y + wv.z * ev.z + wv.w * ev.w;
    }
    g_cpart[b * G4 + g] = acc;
}

// ---------------- generic SGEMM: C[M,N] = A[M,K] * W[N,:K]^T (+bias[n]) (+rowvec[(m>>10)*N+n]) --
// BM=128, BN=64, BK=16, 256 threads, 8x4 register tile. M must be a multiple of 128, K of 16.
template<bool RELU>
__global__ void k_gemm(const float* __restrict__ A, int lda,
                       const float* __restrict__ W, int ldw,
                       const float* __restrict__ bias,
                       const float* __restrict__ rowvec,
                       float* __restrict__ C, int ldc,
                       int N, int K) {
    __shared__ float As[16 * 132];
    __shared__ float Bs[16 * 68];
    int tid = threadIdx.x;
    int bx = blockIdx.x, by = blockIdx.y;
    int tx = tid & 15, ty = tid >> 4;

    float acc[8][4];
#pragma unroll
    for (int i = 0; i < 8; i++)
#pragma unroll
        for (int j = 0; j < 4; j++) acc[i][j] = 0.0f;

    int ml = tid >> 2;              // 0..63
    int kl = (tid & 3) * 4;         // 0,4,8,12
    const float* Abase = A + (long)(by * 128 + ml) * lda + kl;
    int n_load = bx * 64 + ml;      // row of W this thread loads
    const float* Wbase = (n_load < N) ? (W + (long)n_load * ldw + kl) : nullptr;

    for (int kt = 0; kt < K; kt += 16) {
        float4 a0 = *(const float4*)(Abase + kt);
        float4 a1 = *(const float4*)(Abase + kt + (long)64 * lda);
        float4 b0 = make_float4(0.f, 0.f, 0.f, 0.f);
        if (Wbase) b0 = *(const float4*)(Wbase + kt);
        As[(kl + 0) * 132 + ml]      = a0.x;
        As[(kl + 1) * 132 + ml]      = a0.y;
        As[(kl + 2) * 132 + ml]      = a0.z;
        As[(kl + 3) * 132 + ml]      = a0.w;
        As[(kl + 0) * 132 + ml + 64] = a1.x;
        As[(kl + 1) * 132 + ml + 64] = a1.y;
        As[(kl + 2) * 132 + ml + 64] = a1.z;
        As[(kl + 3) * 132 + ml + 64] = a1.w;
        Bs[(kl + 0) * 68 + ml] = b0.x;
        Bs[(kl + 1) * 68 + ml] = b0.y;
        Bs[(kl + 2) * 68 + ml] = b0.z;
        Bs[(kl + 3) * 68 + ml] = b0.w;
        __syncthreads();
#pragma unroll
        for (int k = 0; k < 16; k++) {
            float4 av0 = *(const float4*)&As[k * 132 + ty * 8];
            float4 av1 = *(const float4*)&As[k * 132 + ty * 8 + 4];
            float4 bv  = *(const float4*)&Bs[k * 68 + tx * 4];
            float a[8] = {av0.x, av0.y, av0.z, av0.w, av1.x, av1.y, av1.z, av1.w};
            float bvv[4] = {bv.x, bv.y, bv.z, bv.w};
#pragma unroll
            for (int i = 0; i < 8; i++)
#pragma unroll
                for (int j = 0; j < 4; j++) acc[i][j] += a[i] * bvv[j];
        }
        __syncthreads();
    }

    int m0 = by * 128 + ty * 8, n0 = bx * 64 + tx * 4;
#pragma unroll
    for (int i = 0; i < 8; i++) {
        int m = m0 + i;
        const float* rv = rowvec ? (rowvec + (long)(m >> 10) * N) : nullptr;
#pragma unroll
        for (int j = 0; j < 4; j++) {
            int n = n0 + j;
            if (n < N) {
                float v = acc[i][j];
                if (bias) v += bias[n];
                if (rv)   v += rv[n];
                if (RELU) v = fmaxf(v, 0.0f);
                C[(long)m * ldc + n] = v;
            }
        }
    }
}

// ---------------- persistent LSTM (register-tiled, k-split) ----------------
// 128 CTAs x 256 threads. CTA owns hidden dims j0..j0+3 => 16 gate rows.
// Warp = one of 8 k-slices (64 wide). Thread tile: 4 gate-rows x 4 batches (16 acc).
// Per k: 1 LDS.128 (w, k-major [512][16]) + 1 LDS.128 (h [512][32]) -> 16 FFMA (2B/FMA).
// 8-way k partials reduced through smem; activations, publish, global barrier.
__global__ void k_lstm(const float* __restrict__ pre, const float* __restrict__ Whh) {
    extern __shared__ float sm[];
    float* w_t = sm;                   // [512][16]  k-major weights
    float* h_s = w_t + 512 * 16;       // [512][32]  staged h
    float* ps  = h_s + 512 * 32;       // [8][512]   k-split partials
    float* g_s = ps + 8 * 512;         // [512]      reduced gates (lr*32+b)
    float* c_s = g_s + 512;            // [128]      cell state
    float* hw  = c_s + 128;            // [32][4]    hout staging

    int tid = threadIdx.x;
    int j0  = blockIdx.x * 4;

    // load Whh slice transposed: w_t[k*16 + lr] = Whh[grow(lr)][k],
    // grow(lr) = (lr>>2)*512 + j0 + (lr&3)
    for (int i = tid; i < 16 * 512; i += 256) {
        int lr = i & 15, k = i >> 4;
        int grow = ((lr >> 2) << 9) + j0 + (lr & 3);
        w_t[k * 16 + lr] = Whh[(long)grow * HH + k];
    }
    if (tid < 128) c_s[tid] = 0.0f;
    __syncthreads();

    // compute-role indices
    int kw   = tid >> 5;          // k-slice (warp)
    int lane = tid & 31;
    int rt   = lane >> 3;         // row-group (gate) 0..3
    int bt   = lane & 7;          // batch-group 0..7
    const float4* wb = (const float4*)w_t + (kw * 64) * 4 + rt;
    const float4* hb = (const float4*)h_s + (kw * 64) * 8 + bt;

    // reduce-role indices: outputs o = lr*32 + b
    int o0 = tid, o1 = tid + 256;
    int lr0 = o0 >> 5, b0 = o0 & 31;
    int lr1 = o1 >> 5, b1 = o1 & 31;
    long preoff0 = (long)b0 * LL * G4 + ((lr0 >> 2) << 9) + j0 + (lr0 & 3);
    long preoff1 = (long)b1 * LL * G4 + ((lr1 >> 2) << 9) + j0 + (lr1 & 3);

    for (int t = 0; t < LL; t++) {
        const float4* hin = (const float4*)(g_hbuf + (t & 1) * HH * BB);
        float*        hbn = g_hbuf + ((t + 1) & 1) * HH * BB;

        // prefetch pre-activations for this thread's reduce outputs (hidden by compute)
        float pre0 = __ldg(pre + preoff0 + (long)t * G4);
        float pre1 = __ldg(pre + preoff1 + (long)t * G4);

        // stage full h (L2-coherent: other CTAs wrote it)
        for (int i = tid; i < HH * BB / 4; i += 256)
            *((float4*)h_s + i) = __ldcg(hin + i);
        __syncthreads();

        // 16-acc register tile over 64-wide k-slice
        float a00=0.f,a01=0.f,a02=0.f,a03=0.f;
        float a10=0.f,a11=0.f,a12=0.f,a13=0.f;
        float a20=0.f,a21=0.f,a22=0.f,a23=0.f;
        float a30=0.f,a31=0.f,a32=0.f,a33=0.f;
#pragma unroll 8
        for (int k = 0; k < 64; k++) {
            float4 wv = wb[k * 4];
            float4 hv = hb[k * 8];
            a00 += wv.x * hv.x; a01 += wv.x * hv.y; a02 += wv.x * hv.z; a03 += wv.x * hv.w;
            a10 += wv.y * hv.x; a11 += wv.y * hv.y; a12 += wv.y * hv.z; a13 += wv.y * hv.w;
            a20 += wv.z * hv.x; a21 += wv.z * hv.y; a22 += wv.z * hv.z; a23 += wv.z * hv.w;
            a30 += wv.w * hv.x; a31 += wv.w * hv.y; a32 += wv.w * hv.z; a33 += wv.w * hv.w;
        }
        // store partials: ps[kw][ (rt*4+r)*32 + bt*4 .. ]
        {
            float* pp = ps + kw * 512 + (rt * 4) * 32 + bt * 4;
            *(float4*)(pp)          = make_float4(a00, a01, a02, a03);
            *(float4*)(pp + 32)     = make_float4(a10, a11, a12, a13);
            *(float4*)(pp + 64)     = make_float4(a20, a21, a22, a23);
            *(float4*)(pp + 96)     = make_float4(a30, a31, a32, a33);
        }
        __syncthreads();

        // k-split reduction + pre, 2 outputs per thread
        {
            float gv0 = pre0, gv1 = pre1;
#pragma unroll
            for (int kk = 0; kk < 8; kk++) {
                gv0 += ps[kk * 512 + o0];
                gv1 += ps[kk * 512 + o1];
            }
            g_s[o0] = gv0;
            g_s[o1] = gv1;
        }
        __syncthreads();

        // activations + state update (128 threads, one (jl,b) each)
        if (tid < 128) {
            int jl = tid >> 5, b = tid & 31;
            float gi = g_s[(jl)      * 32 + b];
            float gf = g_s[(4 + jl)  * 32 + b];
            float gg = g_s[(8 + jl)  * 32 + b];
            float go = g_s[(12 + jl) * 32 + b];
            float si = 1.0f / (1.0f + __expf(-gi));
            float sf = 1.0f / (1.0f + __expf(-gf));
            float so = 1.0f / (1.0f + __expf(-go));
            float tg = tanhf(gg);
            float c  = sf * c_s[tid] + si * tg;
            c_s[tid] = c;
            float h  = so * tanhf(c);
            hbn[(j0 + jl) * BB + b] = h;       // publish for next step
            hw[b * 4 + jl] = h;
        }
        __syncthreads();
        // coalesced hout write (float4 per batch row)
        if (tid < 32) {
            float4 v = *(const float4*)&hw[tid * 4];
            *(float4*)(g_hout + ((long)tid * LL + t) * HH + j0) = v;
        }
        __threadfence();
        __syncthreads();
        if (tid == 0) {
            unsigned a = atomicAdd(&g_ctr, 1u);
            if (a == (unsigned)t * NCTA_LSTM + (NCTA_LSTM - 1)) {
                __threadfence();
                atomicExch(&g_gen, (unsigned)(t + 1));
            } else {
                while (*((volatile unsigned*)&g_gen) < (unsigned)(t + 1)) __nanosleep(32);
            }
        }
        __syncthreads();
    }
}

// ---------------- cumsum over time: P[b][t][d] = sum_{s<=t} hout[b][s][d] ----------------
__global__ void k_cumsum() {
    int b = blockIdx.x >> 1;
    int d = ((blockIdx.x & 1) << 8) + threadIdx.x;
    const float* src = g_hout + (long)b * LL * HH + d;
    float* dst = g_P + (long)b * LL * HH + d;
    float acc = 0.0f;
#pragma unroll 4
    for (int t = 0; t < LL; t++) {
        acc += src[(long)t * HH];
        dst[(long)t * HH] = acc;
    }
}

// ---------------- banded online-softmax attention ----------------
__device__ __forceinline__ void upd(float& m, float& l, float4* acc, float sc, const float4* ov) {
    if (sc <= m) {
        float e = __expf(sc - m);
        l += e;
#pragma unroll
        for (int j = 0; j < 4; j++) {
            acc[j].x += e * ov[j].x; acc[j].y += e * ov[j].y;
            acc[j].z += e * ov[j].z; acc[j].w += e * ov[j].w;
        }
    } else {
        float coef = __expf(m - sc);
        l = l * coef + 1.0f;
#pragma unroll
        for (int j = 0; j < 4; j++) {
            acc[j].x = acc[j].x * coef + ov[j].x; acc[j].y = acc[j].y * coef + ov[j].y;
            acc[j].z = acc[j].z * coef + ov[j].z; acc[j].w = acc[j].w * coef + ov[j].w;
        }
        m = sc;
    }
}

__global__ void k_attn() {
    int warp = (blockIdx.x * blockDim.x + threadIdx.x) >> 5;  // 0..16383
    int lane = threadIdx.x & 31;
    int b  = warp >> 9;
    int tp = warp & 511;
    int t0 = tp * 2, t1 = t0 + 1;

    const float* mb = g_mlp  + (long)b * LL * DD;
    const float* ob = g_hout + (long)b * LL * HH;

    float4 q0[4], q1[4], acc0[4], acc1[4];
#pragma unroll
    for (int j = 0; j < 4; j++) {
        q0[j] = *(const float4*)(mb + (long)t0 * DD + lane * 4 + j * 128);
        q1[j] = *(const float4*)(mb + (long)t1 * DD + lane * 4 + j * 128);
        acc0[j] = make_float4(0.f, 0.f, 0.f, 0.f);
        acc1[j] = make_float4(0.f, 0.f, 0.f, 0.f);
    }
    float m0 = -1e30f, m1 = -1e30f, l0 = 0.0f, l1 = 0.0f;

    int slo = t0 - (WIN - 1); if (slo < 0) slo = 0;
    for (int s = slo; s <= t1; s++) {
        float4 ov[4];
        const float* op = ob + (long)s * HH + lane * 4;
#pragma unroll
        for (int j = 0; j < 4; j++) ov[j] = *(const float4*)(op + j * 128);
        float d0 = 0.f, d1 = 0.f;
#pragma unroll
        for (int j = 0; j < 4; j++) {
            d0 += q0[j].x * ov[j].x + q0[j].y * ov[j].y + q0[j].z * ov[j].z + q0[j].w * ov[j].w;
            d1 += q1[j].x * ov[j].x + q1[j].y * ov[j].y + q1[j].z * ov[j].z + q1[j].w * ov[j].w;
        }
#pragma unroll
        for (int off = 16; off; off >>= 1) {
            d0 += __shfl_xor_sync(0xFFFFFFFFu, d0, off);
            d1 += __shfl_xor_sync(0xFFFFFFFFu, d1, off);
        }
        if (s <= t0) {
            float sc = d0 * __expf(-0.6f * (float)(t0 - s));
            upd(m0, l0, acc0, sc, ov);
        }
        if (s >= t1 - (WIN - 1)) {
            float sc = d1 * __expf(-0.6f * (float)(t1 - s));
            upd(m1, l1, acc1, sc, ov);
        }
    }
    // tails: all s <= t-WIN contribute exactly exp(-m) each (fp32-exact vs reference)
    if (t0 >= WIN) {
        float cnt = (float)(t0 - (WIN - 1));
        const float* pp = g_P + ((long)b * LL + (t0 - WIN)) * HH + lane * 4;
        float4 pv[4];
#pragma unroll
        for (int j = 0; j < 4; j++) pv[j] = *(const float4*)(pp + j * 128);
        if (0.0f <= m0) {
            float e = __expf(-m0);
            l0 += cnt * e;
#pragma unroll
            for (int j = 0; j < 4; j++) {
                acc0[j].x += e * pv[j].x; acc0[j].y += e * pv[j].y;
                acc0[j].z += e * pv[j].z; acc0[j].w += e * pv[j].w;
            }
        } else {
            float coef = __expf(m0);
            l0 = l0 * coef + cnt;
#pragma unroll
            for (int j = 0; j < 4; j++) {
                acc0[j].x = acc0[j].x * coef + pv[j].x; acc0[j].y = acc0[j].y * coef + pv[j].y;
                acc0[j].z = acc0[j].z * coef + pv[j].z; acc0[j].w = acc0[j].w * coef + pv[j].w;
            }
            m0 = 0.0f;
        }
    }
    if (t1 >= WIN) {
        float cnt = (float)(t1 - (WIN - 1));
        const float* pp = g_P + ((long)b * LL + (t1 - WIN)) * HH + lane * 4;
        float4 pv[4];
#pragma unroll
        for (int j = 0; j < 4; j++) pv[j] = *(const float4*)(pp + j * 128);
        if (0.0f <= m1) {
            float e = __expf(-m1);
            l1 += cnt * e;
#pragma unroll
            for (int j = 0; j < 4; j++) {
                acc1[j].x += e * pv[j].x; acc1[j].y += e * pv[j].y;
                acc1[j].z += e * pv[j].z; acc1[j].w += e * pv[j].w;
            }
        } else {
            float coef = __expf(m1);
            l1 = l1 * coef + cnt;
#pragma unroll
            for (int j = 0; j < 4; j++) {
                acc1[j].x = acc1[j].x * coef + pv[j].x; acc1[j].y = acc1[j].y * coef + pv[j].y;
                acc1[j].z = acc1[j].z * coef + pv[j].z; acc1[j].w = acc1[j].w * coef + pv[j].w;
            }
            m1 = 0.0f;
        }
    }

    float inv0 = 1.0f / l0, inv1 = 1.0f / l1;
    float* w0 = g_wgt + ((long)b * LL + t0) * HH + lane * 4;
    float* w1 = g_wgt + ((long)b * LL + t1) * HH + lane * 4;
#pragma unroll
    for (int j = 0; j < 4; j++) {
        float4 r0 = make_float4(acc0[j].x * inv0, acc0[j].y * inv0, acc0[j].z * inv0, acc0[j].w * inv0);
        float4 r1 = make_float4(acc1[j].x * inv1, acc1[j].y * inv1, acc1[j].z * inv1, acc1[j].w * inv1);
        *(float4*)(w0 + j * 128) = r0;
        *(float4*)(w1 + j * 128) = r1;
    }
}

// ---------------- launch ----------------
extern "C" void kernel_launch(void* const* d_in, const int* in_sizes, int n_in,
                              void* d_out, int out_size) {
    const float* x        = (const float*)d_in[0];
    const int*   concepts = (const int*)  d_in[1];
    const float* emb      = (const float*)d_in[2];
    const float* Wih      = (const float*)d_in[3];
    const float* Whh      = (const float*)d_in[4];
    const float* bih      = (const float*)d_in[5];
    const float* bhh      = (const float*)d_in[6];
    const float* Wm       = (const float*)d_in[7];
    const float* bm       = (const float*)d_in[8];
    const float* W1       = (const float*)d_in[9];
    const float* b1       = (const float*)d_in[10];
    const float* W2       = (const float*)d_in[11];
    const float* b2       = (const float*)d_in[12];
    float* out = (float*)d_out;

    float *p_pre, *p_cpart, *p_mlp, *p_wgt, *p_h1;
    cudaGetSymbolAddress((void**)&p_pre,   g_pre);
    cudaGetSymbolAddress((void**)&p_cpart, g_cpart);
    cudaGetSymbolAddress((void**)&p_mlp,   g_mlp);
    cudaGetSymbolAddress((void**)&p_wgt,   g_wgt);
    cudaGetSymbolAddress((void**)&p_h1,    g_h1);

    // smem: w_t 32KB + h_s 64KB + ps 16KB + g_s 2KB + c_s 512B + hw 512B
    const int lstm_smem = (512 * 16 + 512 * 32 + 8 * 512 + 512 + 128 + 128) * 4;
    cudaFuncSetAttribute(k_lstm, cudaFuncAttributeMaxDynamicSharedMemorySize, lstm_smem);

    const int M = BB * LL;   // 32768

    k_init<<<128, 256>>>();
    k_cpart<<<BB * 8, 256>>>(emb, concepts, Wih, bih, bhh);
    // pre = x @ WihA^T + cpart   (WihA = first 512 cols of Wih, ldw = 1024)
    k_gemm<false><<<dim3(G4 / 64, M / 128), 256>>>(x, DD, Wih, 2 * DD, nullptr, p_cpart,
                                                   p_pre, G4, G4, DD);
    // mlp = x @ Wm^T + bm
    k_gemm<false><<<dim3(DD / 64, M / 128), 256>>>(x, DD, Wm, DD, bm, nullptr,
                                                   p_mlp, DD, DD, DD);
    // LSTM recurrence
    k_lstm<<<NCTA_LSTM, 256, lstm_smem>>>(p_pre, Whh);
    // prefix sums of h over time
    k_cumsum<<<BB * 2, 256>>>();
    // attention
    k_attn<<<2048, 256>>>();
    // h1 = relu(weighted @ W1^T + b1)
    k_gemm<true><<<dim3(FF / 64, M / 128), 256>>>(p_wgt, HH, W1, HH, b1, nullptr,
                                                  p_h1, FF, FF, HH);
    // res = h1 @ W2^T + b2
    k_gemm<false><<<dim3((OUTD + 63) / 64, M / 128), 256>>>(p_h1, FF, W2, FF, b2, nullptr,
                                                            out, OUTD, OUTD, FF);
}

// round 5
// speedup vs baseline: 1.4224x; 1.0461x over previous
#include <cuda_runtime.h>
#include <cuda_bf16.h>
#include <math.h>

// Problem dims
#define BB   32
#define LL   1024
#define DD   512
#define HH   512
#define G4   2048
#define FF   256
#define OUTD 100
#define NCTA_LSTM 128
#define WIN  64          // exact softmax window; beyond this exp(score*decay - m) == exp(-m) in fp32

// ---------------- scratch (device globals; no allocation) ----------------
__device__ float g_pre  [BB * LL * G4];     // gates pre-activation (x part + cpart)
__device__ float g_cpart[BB * G4];          // concept part + biases
__device__ float g_hout [BB * LL * HH];     // LSTM hidden states
__device__ float g_hbuf [2 * HH * BB];      // h double buffer [buf][k][b]
__device__ float g_mlp  [BB * LL * DD];     // mlp_out
__device__ float g_P    [BB * LL * HH];     // cumsum of hout over t
__device__ float g_csum [BB * 16 * HH];     // per-chunk sums for blocked scan
__device__ float g_wgt  [BB * LL * HH];     // attention output
__device__ float g_h1   [BB * LL * FF];     // relu(W1 ...)
__device__ unsigned g_ctr;
__device__ unsigned g_gen;

// ---------------- f32x2 packed helpers ----------------
__device__ __forceinline__ unsigned long long pk2(float lo, float hi) {
    unsigned long long r;
    asm("mov.b64 %0, {%1, %2};" : "=l"(r) : "f"(lo), "f"(hi));
    return r;
}
__device__ __forceinline__ void ffma2(unsigned long long& d, unsigned long long a,
                                      unsigned long long b) {
    asm("fma.rn.f32x2 %0, %1, %2, %0;" : "+l"(d) : "l"(a), "l"(b));
}

// ---------------- init: zero h buffers + barrier state ----------------
__global__ void k_init() {
    int i = blockIdx.x * 256 + threadIdx.x;
    if (i < 2 * HH * BB) g_hbuf[i] = 0.0f;
    if (i == 0) { g_ctr = 0u; g_gen = 0u; }
}

// ---------------- cpart[b][g] = emb[concepts[b]] . Wih[g][512:1024] + bih[g] + bhh[g] --------
__global__ void k_cpart(const float* __restrict__ emb, const int* __restrict__ concepts,
                        const float* __restrict__ Wih, const float* __restrict__ bih,
                        const float* __restrict__ bhh) {
    int b = blockIdx.x >> 3;
    int g = ((blockIdx.x & 7) << 8) + threadIdx.x;   // 8 chunks * 256
    const float4* e  = (const float4*)(emb + (long)concepts[b] * HH);
    const float4* w  = (const float4*)(Wih + (long)g * (2 * DD) + DD);
    float acc = bih[g] + bhh[g];
#pragma unroll 4
    for (int k = 0; k < HH / 4; k++) {
        float4 wv = __ldg(w + k);
        float4 ev = __ldg(e + k);
        acc += wv.x * ev.x + wv.y * ev.y + wv.z * ev.z + wv.w * ev.w;
    }
    g_cpart[b * G4 + g] = acc;
}

// ---------------- SGEMM: C[M,N] = A[M,K] * W[N,:K]^T (+bias[n]) (+rowvec[(m>>10)*N+n]) ----
// BM=128, BN=128, BK=16, 256 threads, 8x8 register tile (94% FFMA density).
// M multiple of 128, K multiple of 16. N arbitrary (guarded).
template<bool RELU>
__global__ void k_gemm(const float* __restrict__ A, int lda,
                       const float* __restrict__ W, int ldw,
                       const float* __restrict__ bias,
                       const float* __restrict__ rowvec,
                       float* __restrict__ C, int ldc,
                       int N, int K) {
    __shared__ float As[16 * 132];
    __shared__ float Bs[16 * 132];
    int tid = threadIdx.x;
    int bx = blockIdx.x, by = blockIdx.y;
    int tx = tid & 15, ty = tid >> 4;    // tx: n (8 cols), ty: m (8 rows)

    float acc[8][8];
#pragma unroll
    for (int i = 0; i < 8; i++)
#pragma unroll
        for (int j = 0; j < 8; j++) acc[i][j] = 0.0f;

    int row = tid >> 2;              // 0..63
    int kl  = (tid & 3) * 4;         // 0,4,8,12
    const float* Abase = A + (long)(by * 128 + row) * lda + kl;
    int n0l = bx * 128 + row, n1l = n0l + 64;
    const float* W0 = (n0l < N) ? (W + (long)n0l * ldw + kl) : nullptr;
    const float* W1 = (n1l < N) ? (W + (long)n1l * ldw + kl) : nullptr;

    for (int kt = 0; kt < K; kt += 16) {
        float4 a0 = *(const float4*)(Abase + kt);
        float4 a1 = *(const float4*)(Abase + kt + (long)64 * lda);
        float4 b0 = make_float4(0.f, 0.f, 0.f, 0.f);
        float4 b1 = make_float4(0.f, 0.f, 0.f, 0.f);
        if (W0) b0 = *(const float4*)(W0 + kt);
        if (W1) b1 = *(const float4*)(W1 + kt);
#pragma unroll
        for (int q = 0; q < 4; q++) {
            float av0 = q == 0 ? a0.x : q == 1 ? a0.y : q == 2 ? a0.z : a0.w;
            float av1 = q == 0 ? a1.x : q == 1 ? a1.y : q == 2 ? a1.z : a1.w;
            float bv0 = q == 0 ? b0.x : q == 1 ? b0.y : q == 2 ? b0.z : b0.w;
            float bv1 = q == 0 ? b1.x : q == 1 ? b1.y : q == 2 ? b1.z : b1.w;
            As[(kl + q) * 132 + row]      = av0;
            As[(kl + q) * 132 + row + 64] = av1;
            Bs[(kl + q) * 132 + row]      = bv0;
            Bs[(kl + q) * 132 + row + 64] = bv1;
        }
        __syncthreads();
#pragma unroll
        for (int k = 0; k < 16; k++) {
            float4 av0 = *(const float4*)&As[k * 132 + ty * 8];
            float4 av1 = *(const float4*)&As[k * 132 + ty * 8 + 4];
            float4 bv0 = *(const float4*)&Bs[k * 132 + tx * 8];
            float4 bv1 = *(const float4*)&Bs[k * 132 + tx * 8 + 4];
            float a[8] = {av0.x, av0.y, av0.z, av0.w, av1.x, av1.y, av1.z, av1.w};
            float b[8] = {bv0.x, bv0.y, bv0.z, bv0.w, bv1.x, bv1.y, bv1.z, bv1.w};
#pragma unroll
            for (int i = 0; i < 8; i++)
#pragma unroll
                for (int j = 0; j < 8; j++) acc[i][j] += a[i] * b[j];
        }
        __syncthreads();
    }

    int m0 = by * 128 + ty * 8, nn0 = bx * 128 + tx * 8;
#pragma unroll
    for (int i = 0; i < 8; i++) {
        int m = m0 + i;
        const float* rv = rowvec ? (rowvec + (long)(m >> 10) * N) : nullptr;
#pragma unroll
        for (int j = 0; j < 8; j++) {
            int n = nn0 + j;
            if (n < N) {
                float v = acc[i][j];
                if (bias) v += bias[n];
                if (rv)   v += rv[n];
                if (RELU) v = fmaxf(v, 0.0f);
                C[(long)m * ldc + n] = v;
            }
        }
    }
}

// ---------------- persistent LSTM (f32x2-packed, 16-way k-split) ----------------
// 128 CTAs x 256 threads. CTA owns hidden dims j0..j0+3 => 16 gate rows.
// 16 k-slices of width 32 (half-warp each). Thread tile: 8 gate-rows x 4 batches,
// accumulated as 16 f32x2 (row-paired) -> 16 FMA2 + 4 h-packs per k (fma-pipe bound).
// Partials stored coalesced in compute order; reduce threads own linear indices.
__global__ void k_lstm(const float* __restrict__ pre, const float* __restrict__ Whh) {
    extern __shared__ float sm[];
    float* w_t = sm;                   // [512][16]  k-major weights
    float* h_s = w_t + 512 * 16;       // [512][32]  staged h
    float* ps  = h_s + 512 * 32;       // [16][512]  k-split partials (compute order)
    float* g_s = ps + 16 * 512;        // [512]      gates at lr*32 + b
    float* c_s = g_s + 512;            // [128]      cell state
    float* hw  = c_s + 128;            // [32][4]    hout staging

    int tid = threadIdx.x;
    int j0  = blockIdx.x * 4;

    // load Whh slice transposed: w_t[k*16 + lr] = Whh[grow(lr)][k]
    for (int i = tid; i < 16 * 512; i += 256) {
        int lr = i & 15, k = i >> 4;
        int grow = ((lr >> 2) << 9) + j0 + (lr & 3);
        w_t[k * 16 + lr] = Whh[(long)grow * HH + k];
    }
    if (tid < 128) c_s[tid] = 0.0f;

    // compute-role indices
    int ks  = tid >> 4;           // k-slice 0..15 (width 32)
    int l16 = tid & 15;
    int rt  = l16 >> 3;           // row half: rows rt*8 .. rt*8+7
    int bt  = l16 & 7;            // batches bt*4 .. bt*4+3
    const float* wbase = w_t + (ks * 32) * 16 + rt * 8;
    const float* hbase = h_s + (ks * 32) * 32 + bt * 4;

    // reduce-role: thread owns linear partial indices o0=tid, o1=tid+256.
    // decode (lr, b): l = o>>5, idx = o&31; idx = rp*8 + jj*2 + hilo
    int o0 = tid, o1 = tid + 256;
    int lA = o0 >> 5, iA = o0 & 31;
    int lB = o1 >> 5, iB = o1 & 31;
    int lr0 = ((lA >> 3) << 3) + ((iA >> 3) << 1) + (iA & 1);
    int b0  = ((lA & 7) << 2) + ((iA >> 1) & 3);
    int lr1 = ((lB >> 3) << 3) + ((iB >> 3) << 1) + (iB & 1);
    int b1  = ((lB & 7) << 2) + ((iB >> 1) & 3);
    int grow0 = ((lr0 >> 2) << 9) + j0 + (lr0 & 3);
    int grow1 = ((lr1 >> 2) << 9) + j0 + (lr1 & 3);
    long preoff0 = (long)b0 * LL * G4 + grow0;
    long preoff1 = (long)b1 * LL * G4 + grow1;
    int gs0 = lr0 * 32 + b0, gs1 = lr1 * 32 + b1;

    __syncthreads();

    float pre0 = __ldg(pre + preoff0);
    float pre1 = __ldg(pre + preoff1);

    for (int t = 0; t < LL; t++) {
        const float4* hin = (const float4*)(g_hbuf + (t & 1) * HH * BB);
        float*        hbn = g_hbuf + ((t + 1) & 1) * HH * BB;

        // stage full h (L2-coherent; other CTAs wrote it)
#pragma unroll
        for (int i = 0; i < 16; i++)
            *((float4*)h_s + tid + i * 256) = __ldcg(hin + tid + i * 256);
        __syncthreads();

        // 16 f32x2 accumulators: acc[rp][j], rp = row-pair, j = batch
        unsigned long long acc[4][4];
#pragma unroll
        for (int rp = 0; rp < 4; rp++)
#pragma unroll
            for (int j = 0; j < 4; j++) acc[rp][j] = 0ull;

#pragma unroll 4
        for (int k = 0; k < 32; k++) {
            float4 wv0 = *(const float4*)(wbase + k * 16);
            float4 wv1 = *(const float4*)(wbase + k * 16 + 4);
            float4 hv  = *(const float4*)(hbase + k * 32);
            unsigned long long wp0 = pk2(wv0.x, wv0.y);
            unsigned long long wp1 = pk2(wv0.z, wv0.w);
            unsigned long long wp2 = pk2(wv1.x, wv1.y);
            unsigned long long wp3 = pk2(wv1.z, wv1.w);
            unsigned long long h0 = pk2(hv.x, hv.x);
            unsigned long long h1 = pk2(hv.y, hv.y);
            unsigned long long h2 = pk2(hv.z, hv.z);
            unsigned long long h3 = pk2(hv.w, hv.w);
            ffma2(acc[0][0], wp0, h0); ffma2(acc[0][1], wp0, h1);
            ffma2(acc[0][2], wp0, h2); ffma2(acc[0][3], wp0, h3);
            ffma2(acc[1][0], wp1, h0); ffma2(acc[1][1], wp1, h1);
            ffma2(acc[1][2], wp1, h2); ffma2(acc[1][3], wp1, h3);
            ffma2(acc[2][0], wp2, h0); ffma2(acc[2][1], wp2, h1);
            ffma2(acc[2][2], wp2, h2); ffma2(acc[2][3], wp2, h3);
            ffma2(acc[3][0], wp3, h0); ffma2(acc[3][1], wp3, h1);
            ffma2(acc[3][2], wp3, h2); ffma2(acc[3][3], wp3, h3);
        }
        // coalesced partial store: ps[ks*512 + l16*32 + rp*8 + jj*2 + hilo]
        {
            ulonglong2* pp = (ulonglong2*)(ps + ks * 512 + l16 * 32);
#pragma unroll
            for (int rp = 0; rp < 4; rp++) {
                pp[rp * 2 + 0] = make_ulonglong2(acc[rp][0], acc[rp][1]);
                pp[rp * 2 + 1] = make_ulonglong2(acc[rp][2], acc[rp][3]);
            }
        }
        __syncthreads();

        // 16-way k reduction (+pre), conflict-free linear reads
        {
            float gv0 = pre0, gv1 = pre1;
#pragma unroll
            for (int kk = 0; kk < 16; kk++) {
                gv0 += ps[kk * 512 + o0];
                gv1 += ps[kk * 512 + o1];
            }
            g_s[gs0] = gv0;
            g_s[gs1] = gv1;
        }
        __syncthreads();

        // activations + state update (128 threads, one (jl,b) each)
        if (tid < 128) {
            int jl = tid >> 5, b = tid & 31;
            float gi = g_s[(jl)      * 32 + b];
            float gf = g_s[(4 + jl)  * 32 + b];
            float gg = g_s[(8 + jl)  * 32 + b];
            float go = g_s[(12 + jl) * 32 + b];
            float si = 1.0f / (1.0f + __expf(-gi));
            float sf = 1.0f / (1.0f + __expf(-gf));
            float so = 1.0f / (1.0f + __expf(-go));
            float tg = tanhf(gg);
            float c  = sf * c_s[tid] + si * tg;
            c_s[tid] = c;
            float h  = so * tanhf(c);
            hbn[(j0 + jl) * BB + b] = h;       // publish for next step
            hw[b * 4 + jl] = h;
        }
        __syncthreads();
        if (tid < 32) {
            float4 v = *(const float4*)&hw[tid * 4];
            *(float4*)(g_hout + ((long)tid * LL + t) * HH + j0) = v;
        }

        // prefetch next step's pre-activations (hide under barrier)
        if (t + 1 < LL) {
            pre0 = __ldg(pre + preoff0 + (long)(t + 1) * G4);
            pre1 = __ldg(pre + preoff1 + (long)(t + 1) * G4);
        }

        __threadfence();
        __syncthreads();
        if (tid == 0) {
            unsigned a = atomicAdd(&g_ctr, 1u);
            if (a == (unsigned)t * NCTA_LSTM + (NCTA_LSTM - 1)) {
                __threadfence();
                atomicExch(&g_gen, (unsigned)(t + 1));
            }
        }
        // all threads poll the generation flag (no trailing bar.sync)
        while (*((volatile unsigned*)&g_gen) < (unsigned)(t + 1)) { }
        __syncthreads();
    }
}

// ---------------- blocked cumsum: P[b][t][d] = sum_{s<=t} hout[b][s][d] ----------------
__global__ void k_csum1() {      // grid (16, BB): chunk c covers t in [c*64, c*64+64)
    int c = blockIdx.x, b = blockIdx.y;
    int d = threadIdx.x;
    const float* s0 = g_hout + ((long)b * LL + c * 64) * HH + d;
    const float* s1 = s0 + 256;
    float* d0 = g_P + ((long)b * LL + c * 64) * HH + d;
    float* d1 = d0 + 256;
    float a0 = 0.f, a1 = 0.f;
#pragma unroll 8
    for (int t = 0; t < 64; t++) {
        a0 += s0[t * HH]; d0[t * HH] = a0;
        a1 += s1[t * HH]; d1[t * HH] = a1;
    }
    g_csum[((long)b * 16 + c) * HH + d]       = a0;
    g_csum[((long)b * 16 + c) * HH + d + 256] = a1;
}

__global__ void k_csum2() {      // grid (15, BB): chunks 1..15 add exclusive offsets
    int c = blockIdx.x + 1, b = blockIdx.y;
    int d = threadIdx.x;
    float o0 = 0.f, o1 = 0.f;
    for (int cc = 0; cc < c; cc++) {
        o0 += g_csum[((long)b * 16 + cc) * HH + d];
        o1 += g_csum[((long)b * 16 + cc) * HH + d + 256];
    }
    float* d0 = g_P + ((long)b * LL + c * 64) * HH + d;
    float* d1 = d0 + 256;
#pragma unroll 8
    for (int t = 0; t < 64; t++) {
        d0[t * HH] += o0;
        d1[t * HH] += o1;
    }
}

// ---------------- banded online-softmax attention ----------------
__device__ __forceinline__ void upd(float& m, float& l, float4* acc, float sc, const float4* ov) {
    if (sc <= m) {
        float e = __expf(sc - m);
        l += e;
#pragma unroll
        for (int j = 0; j < 4; j++) {
            acc[j].x += e * ov[j].x; acc[j].y += e * ov[j].y;
            acc[j].z += e * ov[j].z; acc[j].w += e * ov[j].w;
        }
    } else {
        float coef = __expf(m - sc);
        l = l * coef + 1.0f;
#pragma unroll
        for (int j = 0; j < 4; j++) {
            acc[j].x = acc[j].x * coef + ov[j].x; acc[j].y = acc[j].y * coef + ov[j].y;
            acc[j].z = acc[j].z * coef + ov[j].z; acc[j].w = acc[j].w * coef + ov[j].w;
        }
        m = sc;
    }
}

__global__ void k_attn() {
    int warp = (blockIdx.x * blockDim.x + threadIdx.x) >> 5;  // 0..16383
    int lane = threadIdx.x & 31;
    int b  = warp >> 9;
    int tp = warp & 511;
    int t0 = tp * 2, t1 = t0 + 1;

    const float* mb = g_mlp  + (long)b * LL * DD;
    const float* ob = g_hout + (long)b * LL * HH;

    float4 q0[4], q1[4], acc0[4], acc1[4];
#pragma unroll
    for (int j = 0; j < 4; j++) {
        q0[j] = *(const float4*)(mb + (long)t0 * DD + lane * 4 + j * 128);
        q1[j] = *(const float4*)(mb + (long)t1 * DD + lane * 4 + j * 128);
        acc0[j] = make_float4(0.f, 0.f, 0.f, 0.f);
        acc1[j] = make_float4(0.f, 0.f, 0.f, 0.f);
    }
    float m0 = -1e30f, m1 = -1e30f, l0 = 0.0f, l1 = 0.0f;

    int slo = t0 - (WIN - 1); if (slo < 0) slo = 0;
    for (int s = slo; s <= t1; s++) {
        float4 ov[4];
        const float* op = ob + (long)s * HH + lane * 4;
#pragma unroll
        for (int j = 0; j < 4; j++) ov[j] = *(const float4*)(op + j * 128);
        float d0 = 0.f, d1 = 0.f;
#pragma unroll
        for (int j = 0; j < 4; j++) {
            d0 += q0[j].x * ov[j].x + q0[j].y * ov[j].y + q0[j].z * ov[j].z + q0[j].w * ov[j].w;
            d1 += q1[j].x * ov[j].x + q1[j].y * ov[j].y + q1[j].z * ov[j].z + q1[j].w * ov[j].w;
        }
#pragma unroll
        for (int off = 16; off; off >>= 1) {
            d0 += __shfl_xor_sync(0xFFFFFFFFu, d0, off);
            d1 += __shfl_xor_sync(0xFFFFFFFFu, d1, off);
        }
        if (s <= t0) {
            float sc = d0 * __expf(-0.6f * (float)(t0 - s));
            upd(m0, l0, acc0, sc, ov);
        }
        if (s >= t1 - (WIN - 1)) {
            float sc = d1 * __expf(-0.6f * (float)(t1 - s));
            upd(m1, l1, acc1, sc, ov);
        }
    }
    // tails: all s <= t-WIN contribute exactly exp(-m) each (fp32-exact vs reference)
    if (t0 >= WIN) {
        float cnt = (float)(t0 - (WIN - 1));
        const float* pp = g_P + ((long)b * LL + (t0 - WIN)) * HH + lane * 4;
        float4 pv[4];
#pragma unroll
        for (int j = 0; j < 4; j++) pv[j] = *(const float4*)(pp + j * 128);
        if (0.0f <= m0) {
            float e = __expf(-m0);
            l0 += cnt * e;
#pragma unroll
            for (int j = 0; j < 4; j++) {
                acc0[j].x += e * pv[j].x; acc0[j].y += e * pv[j].y;
                acc0[j].z += e * pv[j].z; acc0[j].w += e * pv[j].w;
            }
        } else {
            float coef = __expf(m0);
            l0 = l0 * coef + cnt;
#pragma unroll
            for (int j = 0; j < 4; j++) {
                acc0[j].x = acc0[j].x * coef + pv[j].x; acc0[j].y = acc0[j].y * coef + pv[j].y;
                acc0[j].z = acc0[j].z * coef + pv[j].z; acc0[j].w = acc0[j].w * coef + pv[j].w;
            }
            m0 = 0.0f;
        }
    }
    if (t1 >= WIN) {
        float cnt = (float)(t1 - (WIN - 1));
        const float* pp = g_P + ((long)b * LL + (t1 - WIN)) * HH + lane * 4;
        float4 pv[4];
#pragma unroll
        for (int j = 0; j < 4; j++) pv[j] = *(const float4*)(pp + j * 128);
        if (0.0f <= m1) {
            float e = __expf(-m1);
            l1 += cnt * e;
#pragma unroll
            for (int j = 0; j < 4; j++) {
                acc1[j].x += e * pv[j].x; acc1[j].y += e * pv[j].y;
                acc1[j].z += e * pv[j].z; acc1[j].w += e * pv[j].w;
            }
        } else {
            float coef = __expf(m1);
            l1 = l1 * coef + cnt;
#pragma unroll
            for (int j = 0; j < 4; j++) {
                acc1[j].x = acc1[j].x * coef + pv[j].x; acc1[j].y = acc1[j].y * coef + pv[j].y;
                acc1[j].z = acc1[j].z * coef + pv[j].z; acc1[j].w = acc1[j].w * coef + pv[j].w;
            }
            m1 = 0.0f;
        }
    }

    float inv0 = 1.0f / l0, inv1 = 1.0f / l1;
    float* w0 = g_wgt + ((long)b * LL + t0) * HH + lane * 4;
    float* w1 = g_wgt + ((long)b * LL + t1) * HH + lane * 4;
#pragma unroll
    for (int j = 0; j < 4; j++) {
        float4 r0 = make_float4(acc0[j].x * inv0, acc0[j].y * inv0, acc0[j].z * inv0, acc0[j].w * inv0);
        float4 r1 = make_float4(acc1[j].x * inv1, acc1[j].y * inv1, acc1[j].z * inv1, acc1[j].w * inv1);
        *(float4*)(w0 + j * 128) = r0;
        *(float4*)(w1 + j * 128) = r1;
    }
}

// ---------------- launch ----------------
extern "C" void kernel_launch(void* const* d_in, const int* in_sizes, int n_in,
                              void* d_out, int out_size) {
    const float* x        = (const float*)d_in[0];
    const int*   concepts = (const int*)  d_in[1];
    const float* emb      = (const float*)d_in[2];
    const float* Wih      = (const float*)d_in[3];
    const float* Whh      = (const float*)d_in[4];
    const float* bih      = (const float*)d_in[5];
    const float* bhh      = (const float*)d_in[6];
    const float* Wm       = (const float*)d_in[7];
    const float* bm       = (const float*)d_in[8];
    const float* W1       = (const float*)d_in[9];
    const float* b1       = (const float*)d_in[10];
    const float* W2       = (const float*)d_in[11];
    const float* b2       = (const float*)d_in[12];
    float* out = (float*)d_out;

    float *p_pre, *p_cpart, *p_mlp, *p_wgt, *p_h1;
    cudaGetSymbolAddress((void**)&p_pre,   g_pre);
    cudaGetSymbolAddress((void**)&p_cpart, g_cpart);
    cudaGetSymbolAddress((void**)&p_mlp,   g_mlp);
    cudaGetSymbolAddress((void**)&p_wgt,   g_wgt);
    cudaGetSymbolAddress((void**)&p_h1,    g_h1);

    // smem: w_t 32KB + h_s 64KB + ps 32KB + g_s 2KB + c_s 512B + hw 512B = ~131KB
    const int lstm_smem = (512 * 16 + 512 * 32 + 16 * 512 + 512 + 128 + 128) * 4;
    cudaFuncSetAttribute(k_lstm, cudaFuncAttributeMaxDynamicSharedMemorySize, lstm_smem);

    const int M = BB * LL;   // 32768

    k_init<<<128, 256>>>();
    k_cpart<<<BB * 8, 256>>>(emb, concepts, Wih, bih, bhh);
    // pre = x @ WihA^T + cpart   (WihA = first 512 cols of Wih, ldw = 1024)
    k_gemm<false><<<dim3(G4 / 128, M / 128), 256>>>(x, DD, Wih, 2 * DD, nullptr, p_cpart,
                                                    p_pre, G4, G4, DD);
    // mlp = x @ Wm^T + bm
    k_gemm<false><<<dim3(DD / 128, M / 128), 256>>>(x, DD, Wm, DD, bm, nullptr,
                                                    p_mlp, DD, DD, DD);
    // LSTM recurrence
    k_lstm<<<NCTA_LSTM, 256, lstm_smem>>>(p_pre, Whh);
    // blocked prefix sums of h over time
    k_csum1<<<dim3(16, BB), 256>>>();
    k_csum2<<<dim3(15, BB), 256>>>();
    // attention
    k_attn<<<2048, 256>>>();
    // h1 = relu(weighted @ W1^T + b1)
    k_gemm<true><<<dim3(FF / 128, M / 128), 256>>>(p_wgt, HH, W1, HH, b1, nullptr,
                                                   p_h1, FF, FF, HH);
    // res = h1 @ W2^T + b2
    k_gemm<false><<<dim3(1, M / 128), 256>>>(p_h1, FF, W2, FF, b2, nullptr,
                                             out, OUTD, OUTD, FF);
}

// round 6
// speedup vs baseline: 1.4592x; 1.0259x over previous
#include <cuda_runtime.h>
#include <cuda_bf16.h>
#include <math.h>

// Problem dims
#define BB   32
#define LL   1024
#define DD   512
#define HH   512
#define G4   2048
#define FF   256
#define OUTD 100
#define NCTA_LSTM 128
#define WIN  64          // exact softmax window; beyond this exp(score*decay - m) == exp(-m) in fp32

// ---------------- scratch (device globals; no allocation) ----------------
__device__ float g_pre  [BB * LL * G4];     // gates pre-activation (x part + cpart)
__device__ float g_cpart[BB * G4];          // concept part + biases
__device__ float g_hout [BB * LL * HH];     // LSTM hidden states
__device__ float g_hbuf [2 * HH * BB];      // h double buffer [buf][k][b]
__device__ float g_mlp  [BB * LL * DD];     // mlp_out
__device__ float g_P    [BB * LL * HH];     // cumsum of hout over t
__device__ float g_csum [BB * 16 * HH];     // per-chunk sums for blocked scan
__device__ float g_wgt  [BB * LL * HH];     // attention output
__device__ float g_h1   [BB * LL * FF];     // relu(W1 ...)
__device__ unsigned g_flags[NCTA_LSTM * 32]; // per-CTA step flags, 128B apart

// ---------------- f32x2 packed helpers ----------------
__device__ __forceinline__ unsigned long long pk2(float lo, float hi) {
    unsigned long long r;
    asm("mov.b64 %0, {%1, %2};" : "=l"(r) : "f"(lo), "f"(hi));
    return r;
}
__device__ __forceinline__ void ffma2(unsigned long long& d, unsigned long long a,
                                      unsigned long long b) {
    asm("fma.rn.f32x2 %0, %1, %2, %0;" : "+l"(d) : "l"(a), "l"(b));
}
__device__ __forceinline__ unsigned ld_acq(const unsigned* p) {
    unsigned v;
    asm volatile("ld.acquire.gpu.global.u32 %0, [%1];" : "=r"(v) : "l"(p));
    return v;
}
__device__ __forceinline__ void st_rel(unsigned* p, unsigned v) {
    asm volatile("st.release.gpu.global.u32 [%0], %1;" :: "l"(p), "r"(v));
}

// ---------------- init: zero h buffers + barrier state ----------------
__global__ void k_init() {
    int i = blockIdx.x * 256 + threadIdx.x;
    if (i < 2 * HH * BB) g_hbuf[i] = 0.0f;
    if (i < NCTA_LSTM * 32) g_flags[i] = 0u;
}

// ---------------- cpart[b][g] = emb[concepts[b]] . Wih[g][512:1024] + bih[g] + bhh[g] --------
__global__ void k_cpart(const float* __restrict__ emb, const int* __restrict__ concepts,
                        const float* __restrict__ Wih, const float* __restrict__ bih,
                        const float* __restrict__ bhh) {
    int b = blockIdx.x >> 3;
    int g = ((blockIdx.x & 7) << 8) + threadIdx.x;   // 8 chunks * 256
    const float4* e  = (const float4*)(emb + (long)concepts[b] * HH);
    const float4* w  = (const float4*)(Wih + (long)g * (2 * DD) + DD);
    float acc = bih[g] + bhh[g];
#pragma unroll 4
    for (int k = 0; k < HH / 4; k++) {
        float4 wv = __ldg(w + k);
        float4 ev = __ldg(e + k);
        acc += wv.x * ev.x + wv.y * ev.y + wv.z * ev.z + wv.w * ev.w;
    }
    g_cpart[b * G4 + g] = acc;
}

// ---------------- SGEMM: C[M,N] = A[M,K] * W[N,:K]^T (+bias[n]) (+rowvec[(m>>10)*N+n]) ----
// BM=128, BN=128, BK=16, 256 threads, 8x8 register tile.
template<bool RELU>
__global__ void k_gemm(const float* __restrict__ A, int lda,
                       const float* __restrict__ W, int ldw,
                       const float* __restrict__ bias,
                       const float* __restrict__ rowvec,
                       float* __restrict__ C, int ldc,
                       int N, int K) {
    __shared__ float As[16 * 132];
    __shared__ float Bs[16 * 132];
    int tid = threadIdx.x;
    int bx = blockIdx.x, by = blockIdx.y;
    int tx = tid & 15, ty = tid >> 4;    // tx: n (8 cols), ty: m (8 rows)

    float acc[8][8];
#pragma unroll
    for (int i = 0; i < 8; i++)
#pragma unroll
        for (int j = 0; j < 8; j++) acc[i][j] = 0.0f;

    int row = tid >> 2;              // 0..63
    int kl  = (tid & 3) * 4;         // 0,4,8,12
    const float* Abase = A + (long)(by * 128 + row) * lda + kl;
    int n0l = bx * 128 + row, n1l = n0l + 64;
    const float* W0 = (n0l < N) ? (W + (long)n0l * ldw + kl) : nullptr;
    const float* W1 = (n1l < N) ? (W + (long)n1l * ldw + kl) : nullptr;

    for (int kt = 0; kt < K; kt += 16) {
        float4 a0 = *(const float4*)(Abase + kt);
        float4 a1 = *(const float4*)(Abase + kt + (long)64 * lda);
        float4 b0 = make_float4(0.f, 0.f, 0.f, 0.f);
        float4 b1 = make_float4(0.f, 0.f, 0.f, 0.f);
        if (W0) b0 = *(const float4*)(W0 + kt);
        if (W1) b1 = *(const float4*)(W1 + kt);
#pragma unroll
        for (int q = 0; q < 4; q++) {
            float av0 = q == 0 ? a0.x : q == 1 ? a0.y : q == 2 ? a0.z : a0.w;
            float av1 = q == 0 ? a1.x : q == 1 ? a1.y : q == 2 ? a1.z : a1.w;
            float bv0 = q == 0 ? b0.x : q == 1 ? b0.y : q == 2 ? b0.z : b0.w;
            float bv1 = q == 0 ? b1.x : q == 1 ? b1.y : q == 2 ? b1.z : b1.w;
            As[(kl + q) * 132 + row]      = av0;
            As[(kl + q) * 132 + row + 64] = av1;
            Bs[(kl + q) * 132 + row]      = bv0;
            Bs[(kl + q) * 132 + row + 64] = bv1;
        }
        __syncthreads();
#pragma unroll
        for (int k = 0; k < 16; k++) {
            float4 av0 = *(const float4*)&As[k * 132 + ty * 8];
            float4 av1 = *(const float4*)&As[k * 132 + ty * 8 + 4];
            float4 bv0 = *(const float4*)&Bs[k * 132 + tx * 8];
            float4 bv1 = *(const float4*)&Bs[k * 132 + tx * 8 + 4];
            float a[8] = {av0.x, av0.y, av0.z, av0.w, av1.x, av1.y, av1.z, av1.w};
            float b[8] = {bv0.x, bv0.y, bv0.z, bv0.w, bv1.x, bv1.y, bv1.z, bv1.w};
#pragma unroll
            for (int i = 0; i < 8; i++)
#pragma unroll
                for (int j = 0; j < 8; j++) acc[i][j] += a[i] * b[j];
        }
        __syncthreads();
    }

    int m0 = by * 128 + ty * 8, nn0 = bx * 128 + tx * 8;
#pragma unroll
    for (int i = 0; i < 8; i++) {
        int m = m0 + i;
        const float* rv = rowvec ? (rowvec + (long)(m >> 10) * N) : nullptr;
#pragma unroll
        for (int j = 0; j < 8; j++) {
            int n = nn0 + j;
            if (n < N) {
                float v = acc[i][j];
                if (bias) v += bias[n];
                if (rv)   v += rv[n];
                if (RELU) v = fmaxf(v, 0.0f);
                C[(long)m * ldc + n] = v;
            }
        }
    }
}

// ---------------- persistent LSTM (f32x2-packed, distributed-flag barrier) ----------------
// 128 CTAs x 256 threads. CTA owns hidden dims j0..j0+3 => 16 gate rows.
// 16 k-slices of width 32 (half-warp each). Thread tile: 8 gate-rows x 4 batches,
// accumulated as 16 f32x2 (row-paired).
// Barrier: per-CTA flag (128B apart); release store by each CTA, threads 0..127
// each acquire-poll a distinct CTA's flag. No atomics -> no LTS serialization.
__global__ void k_lstm(const float* __restrict__ pre, const float* __restrict__ Whh) {
    extern __shared__ float sm[];
    float* w_t = sm;                   // [512][16]  k-major weights
    float* h_s = w_t + 512 * 16;       // [512][32]  staged h
    float* ps  = h_s + 512 * 32;       // [16][512]  k-split partials (compute order)
    float* g_s = ps + 16 * 512;        // [512]      gates at lr*32 + b
    float* c_s = g_s + 512;            // [128]      cell state
    float* hw  = c_s + 128;            // [32][4]    hout staging

    int tid = threadIdx.x;
    int j0  = blockIdx.x * 4;

    // load Whh slice transposed: w_t[k*16 + lr] = Whh[grow(lr)][k]
    for (int i = tid; i < 16 * 512; i += 256) {
        int lr = i & 15, k = i >> 4;
        int grow = ((lr >> 2) << 9) + j0 + (lr & 3);
        w_t[k * 16 + lr] = Whh[(long)grow * HH + k];
    }
    if (tid < 128) c_s[tid] = 0.0f;

    // compute-role indices
    int ks  = tid >> 4;           // k-slice 0..15 (width 32)
    int l16 = tid & 15;
    int rt  = l16 >> 3;           // row half: rows rt*8 .. rt*8+7
    int bt  = l16 & 7;            // batches bt*4 .. bt*4+3
    const float* wbase = w_t + (ks * 32) * 16 + rt * 8;
    const float* hbase = h_s + (ks * 32) * 32 + bt * 4;

    // reduce-role: thread owns linear partial indices o0=tid, o1=tid+256.
    // decode (lr, b): l = o>>5, idx = o&31; idx = rp*8 + jj*2 + hilo
    int o0 = tid, o1 = tid + 256;
    int lA = o0 >> 5, iA = o0 & 31;
    int lB = o1 >> 5, iB = o1 & 31;
    int lr0 = ((lA >> 3) << 3) + ((iA >> 3) << 1) + (iA & 1);
    int b0  = ((lA & 7) << 2) + ((iA >> 1) & 3);
    int lr1 = ((lB >> 3) << 3) + ((iB >> 3) << 1) + (iB & 1);
    int b1  = ((lB & 7) << 2) + ((iB >> 1) & 3);
    int grow0 = ((lr0 >> 2) << 9) + j0 + (lr0 & 3);
    int grow1 = ((lr1 >> 2) << 9) + j0 + (lr1 & 3);
    long preoff0 = (long)b0 * LL * G4 + grow0;
    long preoff1 = (long)b1 * LL * G4 + grow1;
    int gs0 = lr0 * 32 + b0, gs1 = lr1 * 32 + b1;

    unsigned* myflag  = &g_flags[blockIdx.x * 32];
    const unsigned* pollflag = &g_flags[(tid & 127) * 32];

    __syncthreads();

    float pre0 = __ldg(pre + preoff0);
    float pre1 = __ldg(pre + preoff1);

    for (int t = 0; t < LL; t++) {
        const float4* hin = (const float4*)(g_hbuf + (t & 1) * HH * BB);
        float*        hbn = g_hbuf + ((t + 1) & 1) * HH * BB;

        // stage full h (L2-coherent; other CTAs wrote it)
#pragma unroll
        for (int i = 0; i < 16; i++)
            *((float4*)h_s + tid + i * 256) = __ldcg(hin + tid + i * 256);
        __syncthreads();

        // 16 f32x2 accumulators: acc[rp][j], rp = row-pair, j = batch
        unsigned long long acc[4][4];
#pragma unroll
        for (int rp = 0; rp < 4; rp++)
#pragma unroll
            for (int j = 0; j < 4; j++) acc[rp][j] = 0ull;

#pragma unroll 4
        for (int k = 0; k < 32; k++) {
            float4 wv0 = *(const float4*)(wbase + k * 16);
            float4 wv1 = *(const float4*)(wbase + k * 16 + 4);
            float4 hv  = *(const float4*)(hbase + k * 32);
            unsigned long long wp0 = pk2(wv0.x, wv0.y);
            unsigned long long wp1 = pk2(wv0.z, wv0.w);
            unsigned long long wp2 = pk2(wv1.x, wv1.y);
            unsigned long long wp3 = pk2(wv1.z, wv1.w);
            unsigned long long h0 = pk2(hv.x, hv.x);
            unsigned long long h1 = pk2(hv.y, hv.y);
            unsigned long long h2 = pk2(hv.z, hv.z);
            unsigned long long h3 = pk2(hv.w, hv.w);
            ffma2(acc[0][0], wp0, h0); ffma2(acc[0][1], wp0, h1);
            ffma2(acc[0][2], wp0, h2); ffma2(acc[0][3], wp0, h3);
            ffma2(acc[1][0], wp1, h0); ffma2(acc[1][1], wp1, h1);
            ffma2(acc[1][2], wp1, h2); ffma2(acc[1][3], wp1, h3);
            ffma2(acc[2][0], wp2, h0); ffma2(acc[2][1], wp2, h1);
            ffma2(acc[2][2], wp2, h2); ffma2(acc[2][3], wp2, h3);
            ffma2(acc[3][0], wp3, h0); ffma2(acc[3][1], wp3, h1);
            ffma2(acc[3][2], wp3, h2); ffma2(acc[3][3], wp3, h3);
        }
        // coalesced partial store: ps[ks*512 + l16*32 + rp*8 + jj*2 + hilo]
        {
            ulonglong2* pp = (ulonglong2*)(ps + ks * 512 + l16 * 32);
#pragma unroll
            for (int rp = 0; rp < 4; rp++) {
                pp[rp * 2 + 0] = make_ulonglong2(acc[rp][0], acc[rp][1]);
                pp[rp * 2 + 1] = make_ulonglong2(acc[rp][2], acc[rp][3]);
            }
        }
        __syncthreads();

        // 16-way k reduction (+pre), conflict-free linear reads
        {
            float gv0 = pre0, gv1 = pre1;
#pragma unroll
            for (int kk = 0; kk < 16; kk++) {
                gv0 += ps[kk * 512 + o0];
                gv1 += ps[kk * 512 + o1];
            }
            g_s[gs0] = gv0;
            g_s[gs1] = gv1;
        }
        __syncthreads();

        // activations + state update (128 threads, one (jl,b) each)
        if (tid < 128) {
            int jl = tid >> 5, b = tid & 31;
            float gi = g_s[(jl)      * 32 + b];
            float gf = g_s[(4 + jl)  * 32 + b];
            float gg = g_s[(8 + jl)  * 32 + b];
            float go = g_s[(12 + jl) * 32 + b];
            float si = 1.0f / (1.0f + __expf(-gi));
            float sf = 1.0f / (1.0f + __expf(-gf));
            float so = 1.0f / (1.0f + __expf(-go));
            float tg = tanhf(gg);
            float c  = sf * c_s[tid] + si * tg;
            c_s[tid] = c;
            float h  = so * tanhf(c);
            hbn[(j0 + jl) * BB + b] = h;       // publish for next step
            hw[b * 4 + jl] = h;
        }
        __syncthreads();
        if (tid < 32) {
            float4 v = *(const float4*)&hw[tid * 4];
            *(float4*)(g_hout + ((long)tid * LL + t) * HH + j0) = v;
        }

        // ---- distributed-flag barrier ----
        __threadfence();                 // h stores visible GPU-wide
        __syncthreads();                 // all CTA threads fenced
        if (tid == 0) st_rel(myflag, (unsigned)(t + 1));

        // prefetch next step's pre-activations under the wait
        if (t + 1 < LL) {
            pre0 = __ldg(pre + preoff0 + (long)(t + 1) * G4);
            pre1 = __ldg(pre + preoff1 + (long)(t + 1) * G4);
        }

        if (tid < NCTA_LSTM) {
            while (ld_acq(pollflag) < (unsigned)(t + 1)) { }
        }
        __syncthreads();
    }
}

// ---------------- blocked cumsum: P[b][t][d] = sum_{s<=t} hout[b][s][d] ----------------
__global__ void k_csum1() {      // grid (16, BB): chunk c covers t in [c*64, c*64+64)
    int c = blockIdx.x, b = blockIdx.y;
    int d = threadIdx.x;
    const float* s0 = g_hout + ((long)b * LL + c * 64) * HH + d;
    const float* s1 = s0 + 256;
    float* d0 = g_P + ((long)b * LL + c * 64) * HH + d;
    float* d1 = d0 + 256;
    float a0 = 0.f, a1 = 0.f;
#pragma unroll 8
    for (int t = 0; t < 64; t++) {
        a0 += s0[t * HH]; d0[t * HH] = a0;
        a1 += s1[t * HH]; d1[t * HH] = a1;
    }
    g_csum[((long)b * 16 + c) * HH + d]       = a0;
    g_csum[((long)b * 16 + c) * HH + d + 256] = a1;
}

__global__ void k_csum2() {      // grid (15, BB): chunks 1..15 add exclusive offsets
    int c = blockIdx.x + 1, b = blockIdx.y;
    int d = threadIdx.x;
    float o0 = 0.f, o1 = 0.f;
    for (int cc = 0; cc < c; cc++) {
        o0 += g_csum[((long)b * 16 + cc) * HH + d];
        o1 += g_csum[((long)b * 16 + cc) * HH + d + 256];
    }
    float* d0 = g_P + ((long)b * LL + c * 64) * HH + d;
    float* d1 = d0 + 256;
#pragma unroll 8
    for (int t = 0; t < 64; t++) {
        d0[t * HH] += o0;
        d1[t * HH] += o1;
    }
}

// ---------------- banded online-softmax attention ----------------
__device__ __forceinline__ void upd(float& m, float& l, float4* acc, float sc, const float4* ov) {
    if (sc <= m) {
        float e = __expf(sc - m);
        l += e;
#pragma unroll
        for (int j = 0; j < 4; j++) {
            acc[j].x += e * ov[j].x; acc[j].y += e * ov[j].y;
            acc[j].z += e * ov[j].z; acc[j].w += e * ov[j].w;
        }
    } else {
        float coef = __expf(m - sc);
        l = l * coef + 1.0f;
#pragma unroll
        for (int j = 0; j < 4; j++) {
            acc[j].x = acc[j].x * coef + ov[j].x; acc[j].y = acc[j].y * coef + ov[j].y;
            acc[j].z = acc[j].z * coef + ov[j].z; acc[j].w = acc[j].w * coef + ov[j].w;
        }
        m = sc;
    }
}

__global__ void k_attn() {
    int warp = (blockIdx.x * blockDim.x + threadIdx.x) >> 5;  // 0..16383
    int lane = threadIdx.x & 31;
    int b  = warp >> 9;
    int tp = warp & 511;
    int t0 = tp * 2, t1 = t0 + 1;

    const float* mb = g_mlp  + (long)b * LL * DD;
    const float* ob = g_hout + (long)b * LL * HH;

    float4 q0[4], q1[4], acc0[4], acc1[4];
#pragma unroll
    for (int j = 0; j < 4; j++) {
        q0[j] = *(const float4*)(mb + (long)t0 * DD + lane * 4 + j * 128);
        q1[j] = *(const float4*)(mb + (long)t1 * DD + lane * 4 + j * 128);
        acc0[j] = make_float4(0.f, 0.f, 0.f, 0.f);
        acc1[j] = make_float4(0.f, 0.f, 0.f, 0.f);
    }
    float m0 = -1e30f, m1 = -1e30f, l0 = 0.0f, l1 = 0.0f;

    int slo = t0 - (WIN - 1); if (slo < 0) slo = 0;
    for (int s = slo; s <= t1; s++) {
        float4 ov[4];
        const float* op = ob + (long)s * HH + lane * 4;
#pragma unroll
        for (int j = 0; j < 4; j++) ov[j] = *(const float4*)(op + j * 128);
        float d0 = 0.f, d1 = 0.f;
#pragma unroll
        for (int j = 0; j < 4; j++) {
            d0 += q0[j].x * ov[j].x + q0[j].y * ov[j].y + q0[j].z * ov[j].z + q0[j].w * ov[j].w;
            d1 += q1[j].x * ov[j].x + q1[j].y * ov[j].y + q1[j].z * ov[j].z + q1[j].w * ov[j].w;
        }
#pragma unroll
        for (int off = 16; off; off >>= 1) {
            d0 += __shfl_xor_sync(0xFFFFFFFFu, d0, off);
            d1 += __shfl_xor_sync(0xFFFFFFFFu, d1, off);
        }
        if (s <= t0) {
            float sc = d0 * __expf(-0.6f * (float)(t0 - s));
            upd(m0, l0, acc0, sc, ov);
        }
        if (s >= t1 - (WIN - 1)) {
            float sc = d1 * __expf(-0.6f * (float)(t1 - s));
            upd(m1, l1, acc1, sc, ov);
        }
    }
    // tails: all s <= t-WIN contribute exactly exp(-m) each (fp32-exact vs reference)
    if (t0 >= WIN) {
        float cnt = (float)(t0 - (WIN - 1));
        const float* pp = g_P + ((long)b * LL + (t0 - WIN)) * HH + lane * 4;
        float4 pv[4];
#pragma unroll
        for (int j = 0; j < 4; j++) pv[j] = *(const float4*)(pp + j * 128);
        if (0.0f <= m0) {
            float e = __expf(-m0);
            l0 += cnt * e;
#pragma unroll
            for (int j = 0; j < 4; j++) {
                acc0[j].x += e * pv[j].x; acc0[j].y += e * pv[j].y;
                acc0[j].z += e * pv[j].z; acc0[j].w += e * pv[j].w;
            }
        } else {
            float coef = __expf(m0);
            l0 = l0 * coef + cnt;
#pragma unroll
            for (int j = 0; j < 4; j++) {
                acc0[j].x = acc0[j].x * coef + pv[j].x; acc0[j].y = acc0[j].y * coef + pv[j].y;
                acc0[j].z = acc0[j].z * coef + pv[j].z; acc0[j].w = acc0[j].w * coef + pv[j].w;
            }
            m0 = 0.0f;
        }
    }
    if (t1 >= WIN) {
        float cnt = (float)(t1 - (WIN - 1));
        const float* pp = g_P + ((long)b * LL + (t1 - WIN)) * HH + lane * 4;
        float4 pv[4];
#pragma unroll
        for (int j = 0; j < 4; j++) pv[j] = *(const float4*)(pp + j * 128);
        if (0.0f <= m1) {
            float e = __expf(-m1);
            l1 += cnt * e;
#pragma unroll
            for (int j = 0; j < 4; j++) {
                acc1[j].x += e * pv[j].x; acc1[j].y += e * pv[j].y;
                acc1[j].z += e * pv[j].z; acc1[j].w += e * pv[j].w;
            }
        } else {
            float coef = __expf(m1);
            l1 = l1 * coef + cnt;
#pragma unroll
            for (int j = 0; j < 4; j++) {
                acc1[j].x = acc1[j].x * coef + pv[j].x; acc1[j].y = acc1[j].y * coef + pv[j].y;
                acc1[j].z = acc1[j].z * coef + pv[j].z; acc1[j].w = acc1[j].w * coef + pv[j].w;
            }
            m1 = 0.0f;
        }
    }

    float inv0 = 1.0f / l0, inv1 = 1.0f / l1;
    float* w0 = g_wgt + ((long)b * LL + t0) * HH + lane * 4;
    float* w1 = g_wgt + ((long)b * LL + t1) * HH + lane * 4;
#pragma unroll
    for (int j = 0; j < 4; j++) {
        float4 r0 = make_float4(acc0[j].x * inv0, acc0[j].y * inv0, acc0[j].z * inv0, acc0[j].w * inv0);
        float4 r1 = make_float4(acc1[j].x * inv1, acc1[j].y * inv1, acc1[j].z * inv1, acc1[j].w * inv1);
        *(float4*)(w0 + j * 128) = r0;
        *(float4*)(w1 + j * 128) = r1;
    }
}

// ---------------- launch ----------------
extern "C" void kernel_launch(void* const* d_in, const int* in_sizes, int n_in,
                              void* d_out, int out_size) {
    const float* x        = (const float*)d_in[0];
    const int*   concepts = (const int*)  d_in[1];
    const float* emb      = (const float*)d_in[2];
    const float* Wih      = (const float*)d_in[3];
    const float* Whh      = (const float*)d_in[4];
    const float* bih      = (const float*)d_in[5];
    const float* bhh      = (const float*)d_in[6];
    const float* Wm       = (const float*)d_in[7];
    const float* bm       = (const float*)d_in[8];
    const float* W1       = (const float*)d_in[9];
    const float* b1       = (const float*)d_in[10];
    const float* W2       = (const float*)d_in[11];
    const float* b2       = (const float*)d_in[12];
    float* out = (float*)d_out;

    float *p_pre, *p_cpart, *p_mlp, *p_wgt, *p_h1;
    cudaGetSymbolAddress((void**)&p_pre,   g_pre);
    cudaGetSymbolAddress((void**)&p_cpart, g_cpart);
    cudaGetSymbolAddress((void**)&p_mlp,   g_mlp);
    cudaGetSymbolAddress((void**)&p_wgt,   g_wgt);
    cudaGetSymbolAddress((void**)&p_h1,    g_h1);

    // smem: w_t 32KB + h_s 64KB + ps 32KB + g_s 2KB + c_s 512B + hw 512B = ~131KB
    const int lstm_smem = (512 * 16 + 512 * 32 + 16 * 512 + 512 + 128 + 128) * 4;
    cudaFuncSetAttribute(k_lstm, cudaFuncAttributeMaxDynamicSharedMemorySize, lstm_smem);

    const int M = BB * LL;   // 32768

    k_init<<<128, 256>>>();
    k_cpart<<<BB * 8, 256>>>(emb, concepts, Wih, bih, bhh);
    // pre = x @ WihA^T + cpart   (WihA = first 512 cols of Wih, ldw = 1024)
    k_gemm<false><<<dim3(G4 / 128, M / 128), 256>>>(x, DD, Wih, 2 * DD, nullptr, p_cpart,
                                                    p_pre, G4, G4, DD);
    // mlp = x @ Wm^T + bm
    k_gemm<false><<<dim3(DD / 128, M / 128), 256>>>(x, DD, Wm, DD, bm, nullptr,
                                                    p_mlp, DD, DD, DD);
    // LSTM recurrence
    k_lstm<<<NCTA_LSTM, 256, lstm_smem>>>(p_pre, Whh);
    // blocked prefix sums of h over time
    k_csum1<<<dim3(16, BB), 256>>>();
    k_csum2<<<dim3(15, BB), 256>>>();
    // attention
    k_attn<<<2048, 256>>>();
    // h1 = relu(weighted @ W1^T + b1)
    k_gemm<true><<<dim3(FF / 128, M / 128), 256>>>(p_wgt, HH, W1, HH, b1, nullptr,
                                                   p_h1, FF, FF, HH);
    // res = h1 @ W2^T + b2
    k_gemm<false><<<dim3(1, M / 128), 256>>>(p_h1, FF, W2, FF, b2, nullptr,
                                             out, OUTD, OUTD, FF);
}

// round 7
// speedup vs baseline: 1.6024x; 1.0981x over previous
#include <cuda_runtime.h>
#include <cuda_bf16.h>
#include <math.h>

// Problem dims
#define BB   32
#define LL   1024
#define DD   512
#define HH   512
#define G4   2048
#define FF   256
#define OUTD 100
#define NCTA_LSTM 128
#define WIN  64          // exact softmax window; beyond this exp(score*decay - m) == exp(-m) in fp32

// ---------------- scratch (device globals; no allocation) ----------------
__device__ float g_pre  [BB * LL * G4];     // gates pre-activation, PERMUTED: [b][t][j*4+gate]
__device__ float g_cpart[BB * G4];          // concept part + biases (original gate order)
__device__ float g_hout [BB * LL * HH];     // LSTM hidden states
__device__ float g_hbuf [2 * HH * BB];      // h double buffer [buf][k][b]
__device__ float g_mlp  [BB * LL * DD];     // mlp_out
__device__ float g_P    [BB * LL * HH];     // cumsum of hout over t
__device__ float g_csum [BB * 16 * HH];     // per-chunk sums for blocked scan
__device__ float g_wgt  [BB * LL * HH];     // attention output
__device__ float g_h1   [BB * LL * FF];     // relu(W1 ...)
__device__ unsigned g_flags[NCTA_LSTM * 32]; // per-CTA step flags, 128B apart

// ---------------- f32x2 packed helpers ----------------
__device__ __forceinline__ unsigned long long pk2(float lo, float hi) {
    unsigned long long r;
    asm("mov.b64 %0, {%1, %2};" : "=l"(r) : "f"(lo), "f"(hi));
    return r;
}
__device__ __forceinline__ void ffma2(unsigned long long& d, unsigned long long a,
                                      unsigned long long b) {
    asm("fma.rn.f32x2 %0, %1, %2, %0;" : "+l"(d) : "l"(a), "l"(b));
}
__device__ __forceinline__ unsigned ld_acq(const unsigned* p) {
    unsigned v;
    asm volatile("ld.acquire.gpu.global.u32 %0, [%1];" : "=r"(v) : "l"(p));
    return v;
}
__device__ __forceinline__ void st_rel(unsigned* p, unsigned v) {
    asm volatile("st.release.gpu.global.u32 [%0], %1;" :: "l"(p), "r"(v));
}

// ---------------- init: zero h buffers + barrier state ----------------
__global__ void k_init() {
    int i = blockIdx.x * 256 + threadIdx.x;
    if (i < 2 * HH * BB) g_hbuf[i] = 0.0f;
    if (i < NCTA_LSTM * 32) g_flags[i] = 0u;
}

// ---------------- cpart[b][g] = emb[concepts[b]] . Wih[g][512:1024] + bih[g] + bhh[g] --------
__global__ void k_cpart(const float* __restrict__ emb, const int* __restrict__ concepts,
                        const float* __restrict__ Wih, const float* __restrict__ bih,
                        const float* __restrict__ bhh) {
    int b = blockIdx.x >> 3;
    int g = ((blockIdx.x & 7) << 8) + threadIdx.x;   // 8 chunks * 256
    const float4* e  = (const float4*)(emb + (long)concepts[b] * HH);
    const float4* w  = (const float4*)(Wih + (long)g * (2 * DD) + DD);
    float acc = bih[g] + bhh[g];
#pragma unroll 4
    for (int k = 0; k < HH / 4; k++) {
        float4 wv = __ldg(w + k);
        float4 ev = __ldg(e + k);
        acc += wv.x * ev.x + wv.y * ev.y + wv.z * ev.z + wv.w * ev.w;
    }
    g_cpart[b * G4 + g] = acc;
}

// ---------------- SGEMM: C[M,N] = A[M,K] * W[N,:K]^T (+bias[n]) (+rowvec[(m>>10)*N+n]) ----
// BM=128, BN=128, BK=16, 256 threads, 8x8 register tile.
// PERM: write output column n at permuted position ((n&511)*4 + (n>>9)) -- groups the
// 4 gates of one hidden unit contiguously for the LSTM's float4 bias load.
template<bool RELU, bool PERM>
__global__ void k_gemm(const float* __restrict__ A, int lda,
                       const float* __restrict__ W, int ldw,
                       const float* __restrict__ bias,
                       const float* __restrict__ rowvec,
                       float* __restrict__ C, int ldc,
                       int N, int K) {
    __shared__ float As[16 * 132];
    __shared__ float Bs[16 * 132];
    int tid = threadIdx.x;
    int bx = blockIdx.x, by = blockIdx.y;
    int tx = tid & 15, ty = tid >> 4;    // tx: n (8 cols), ty: m (8 rows)

    float acc[8][8];
#pragma unroll
    for (int i = 0; i < 8; i++)
#pragma unroll
        for (int j = 0; j < 8; j++) acc[i][j] = 0.0f;

    int row = tid >> 2;              // 0..63
    int kl  = (tid & 3) * 4;         // 0,4,8,12
    const float* Abase = A + (long)(by * 128 + row) * lda + kl;
    int n0l = bx * 128 + row, n1l = n0l + 64;
    const float* W0 = (n0l < N) ? (W + (long)n0l * ldw + kl) : nullptr;
    const float* W1 = (n1l < N) ? (W + (long)n1l * ldw + kl) : nullptr;

    for (int kt = 0; kt < K; kt += 16) {
        float4 a0 = *(const float4*)(Abase + kt);
        float4 a1 = *(const float4*)(Abase + kt + (long)64 * lda);
        float4 b0 = make_float4(0.f, 0.f, 0.f, 0.f);
        float4 b1 = make_float4(0.f, 0.f, 0.f, 0.f);
        if (W0) b0 = *(const float4*)(W0 + kt);
        if (W1) b1 = *(const float4*)(W1 + kt);
#pragma unroll
        for (int q = 0; q < 4; q++) {
            float av0 = q == 0 ? a0.x : q == 1 ? a0.y : q == 2 ? a0.z : a0.w;
            float av1 = q == 0 ? a1.x : q == 1 ? a1.y : q == 2 ? a1.z : a1.w;
            float bv0 = q == 0 ? b0.x : q == 1 ? b0.y : q == 2 ? b0.z : b0.w;
            float bv1 = q == 0 ? b1.x : q == 1 ? b1.y : q == 2 ? b1.z : b1.w;
            As[(kl + q) * 132 + row]      = av0;
            As[(kl + q) * 132 + row + 64] = av1;
            Bs[(kl + q) * 132 + row]      = bv0;
            Bs[(kl + q) * 132 + row + 64] = bv1;
        }
        __syncthreads();
#pragma unroll
        for (int k = 0; k < 16; k++) {
            float4 av0 = *(const float4*)&As[k * 132 + ty * 8];
            float4 av1 = *(const float4*)&As[k * 132 + ty * 8 + 4];
            float4 bv0 = *(const float4*)&Bs[k * 132 + tx * 8];
            float4 bv1 = *(const float4*)&Bs[k * 132 + tx * 8 + 4];
            float a[8] = {av0.x, av0.y, av0.z, av0.w, av1.x, av1.y, av1.z, av1.w};
            float b[8] = {bv0.x, bv0.y, bv0.z, bv0.w, bv1.x, bv1.y, bv1.z, bv1.w};
#pragma unroll
            for (int i = 0; i < 8; i++)
#pragma unroll
                for (int j = 0; j < 8; j++) acc[i][j] += a[i] * b[j];
        }
        __syncthreads();
    }

    int m0 = by * 128 + ty * 8, nn0 = bx * 128 + tx * 8;
#pragma unroll
    for (int i = 0; i < 8; i++) {
        int m = m0 + i;
        const float* rv = rowvec ? (rowvec + (long)(m >> 10) * N) : nullptr;
#pragma unroll
        for (int j = 0; j < 8; j++) {
            int n = nn0 + j;
            if (n < N) {
                float v = acc[i][j];
                if (bias) v += bias[n];
                if (rv)   v += rv[n];
                if (RELU) v = fmaxf(v, 0.0f);
                int np = PERM ? (((n & 511) << 2) | (n >> 9)) : n;
                C[(long)m * ldc + np] = v;
            }
        }
    }
}

// ---------------- persistent LSTM (per-warp producer polling, fused reduce+act) --------
// 128 CTAs x 256 threads. CTA owns hidden dims j0..j0+3 => 16 gate rows.
// Warp w consumes h rows [64w, 64w+64) = output of CTAs 16w..16w+15 only:
// each warp polls its 16 producer flags, stages its own 8KB, computes -- no
// CTA-wide sync until the partial reduction. Two __syncthreads per step.
// Partials swizzled in smem so 128 act-threads read 4 gates x 16 k-partials directly.
__global__ void __launch_bounds__(256, 1)
k_lstm(const float* __restrict__ pre, const float* __restrict__ Whh) {
    extern __shared__ float sm[];
    float* w_t = sm;                   // [512][16]  k-major weights
    float* h_s = w_t + 512 * 16;       // [512][32]  staged h
    float* ps  = h_s + 512 * 32;       // [16][512]  swizzled k-split partials
    float* c_s = ps + 16 * 512;        // [128]      cell state

    int tid  = threadIdx.x;
    int j0   = blockIdx.x * 4;
    int w    = tid >> 5;
    int lane = tid & 31;

    // load Whh slice transposed: w_t[k*16 + lr] = Whh[grow(lr)][k]
    for (int i = tid; i < 16 * 512; i += 256) {
        int lr = i & 15, k = i >> 4;
        int grow = ((lr >> 2) << 9) + j0 + (lr & 3);
        w_t[k * 16 + lr] = Whh[(long)grow * HH + k];
    }
    if (tid < 128) c_s[tid] = 0.0f;

    // compute-role indices
    int ks  = tid >> 4;           // k-slice 0..15 (width 32); warp w owns ks in {2w, 2w+1}
    int l16 = tid & 15;
    int rt  = l16 >> 3;           // row half
    int bt  = l16 & 7;            // batch group of 4
    int rowid = rt * 8 + bt;
    int xlow  = ((rowid >> 2) & 1) << 2;
    const float* wbase = w_t + (ks * 32) * 16 + rt * 8;
    const float* hbase = h_s + (ks * 32) * 32 + bt * 4;
    float* psbase = ps + ks * 512 + rowid * 32;

    // activation-role (tid < 128): hidden jl = tid>>5, batch ab = tid&31
    int jl = tid >> 5, ab = tid & 31;
    long preoff = (long)ab * LL * G4 + (j0 + jl) * 4;    // permuted pre: float4 of 4 gates
    int low_r = (((ab & 3) << 1) | (jl & 1)) ^ (((ab >> 4) & 1) << 2);
    int gbase[4];
#pragma unroll
    for (int g = 0; g < 4; g++) {
        int rp   = (g * 2 + (jl >> 1)) & 3;
        int slot = rp ^ ((ab >> 2) & 3);
        gbase[g] = (g >> 1) * 256 + (ab >> 2) * 32 + slot * 8 + low_r;
    }

    unsigned* myflag = &g_flags[blockIdx.x * 32];
    const unsigned* pollflag = &g_flags[(w * 16 + (lane & 15)) * 32];

    __syncthreads();

    float4 pf4 = make_float4(0.f, 0.f, 0.f, 0.f);
    if (tid < 128) pf4 = *(const float4*)(pre + preoff);    // t = 0

    for (int t = 0; t < LL; t++) {
        // ---- per-warp: wait for this warp's 16 producers, stage own h rows ----
        while (ld_acq(pollflag) < (unsigned)t) { }
        __syncwarp();
        {
            const float4* hin  = (const float4*)(g_hbuf + (t & 1) * HH * BB) + w * 512;
            float4*       hdst = (float4*)h_s + w * 512;
#pragma unroll
            for (int i = 0; i < 16; i++)
                hdst[lane + 32 * i] = __ldcg(hin + lane + 32 * i);
        }
        __syncwarp();

        // ---- compute: 16 f32x2 accumulators over own 32-wide k-slice ----
        unsigned long long acc[4][4];
#pragma unroll
        for (int rp = 0; rp < 4; rp++)
#pragma unroll
            for (int j = 0; j < 4; j++) acc[rp][j] = 0ull;

#pragma unroll 4
        for (int k = 0; k < 32; k++) {
            float4 wv0 = *(const float4*)(wbase + k * 16);
            float4 wv1 = *(const float4*)(wbase + k * 16 + 4);
            float4 hv  = *(const float4*)(hbase + k * 32);
            unsigned long long wp0 = pk2(wv0.x, wv0.y);
            unsigned long long wp1 = pk2(wv0.z, wv0.w);
            unsigned long long wp2 = pk2(wv1.x, wv1.y);
            unsigned long long wp3 = pk2(wv1.z, wv1.w);
            unsigned long long h0 = pk2(hv.x, hv.x);
            unsigned long long h1 = pk2(hv.y, hv.y);
            unsigned long long h2 = pk2(hv.z, hv.z);
            unsigned long long h3 = pk2(hv.w, hv.w);
            ffma2(acc[0][0], wp0, h0); ffma2(acc[0][1], wp0, h1);
            ffma2(acc[0][2], wp0, h2); ffma2(acc[0][3], wp0, h3);
            ffma2(acc[1][0], wp1, h0); ffma2(acc[1][1], wp1, h1);
            ffma2(acc[1][2], wp1, h2); ffma2(acc[1][3], wp1, h3);
            ffma2(acc[2][0], wp2, h0); ffma2(acc[2][1], wp2, h1);
            ffma2(acc[2][2], wp2, h2); ffma2(acc[2][3], wp2, h3);
            ffma2(acc[3][0], wp3, h0); ffma2(acc[3][1], wp3, h1);
            ffma2(acc[3][2], wp3, h2); ffma2(acc[3][3], wp3, h3);
        }
        // swizzled partial store (16B chunks; slot = rp^(rowid&3), chunk low ^= xlow)
#pragma unroll
        for (int rp = 0; rp < 4; rp++) {
            int slot = rp ^ (rowid & 3);
            *(ulonglong2*)(psbase + slot * 8 + (0 ^ xlow)) =
                make_ulonglong2(acc[rp][0], acc[rp][1]);
            *(ulonglong2*)(psbase + slot * 8 + (4 ^ xlow)) =
                make_ulonglong2(acc[rp][2], acc[rp][3]);
        }
        __syncthreads();

        // ---- fused reduce + activation + publish (tid < 128) ----
        if (tid < 128) {
            float gs0 = 0.f, gs1 = 0.f, gs2 = 0.f, gs3 = 0.f;
#pragma unroll
            for (int kk = 0; kk < 16; kk++) {
                const float* pk = ps + kk * 512;
                gs0 += pk[gbase[0]];
                gs1 += pk[gbase[1]];
                gs2 += pk[gbase[2]];
                gs3 += pk[gbase[3]];
            }
            float gi = gs0 + pf4.x;
            float gf = gs1 + pf4.y;
            float gg = gs2 + pf4.z;
            float go = gs3 + pf4.w;
            float si = 1.0f / (1.0f + __expf(-gi));
            float sf = 1.0f / (1.0f + __expf(-gf));
            float so = 1.0f / (1.0f + __expf(-go));
            float tg = tanhf(gg);
            float c  = sf * c_s[tid] + si * tg;
            c_s[tid] = c;
            float h  = so * tanhf(c);
            g_hbuf[((t + 1) & 1) * HH * BB + (j0 + jl) * BB + ab] = h;  // coalesced per warp
            g_hout[((long)ab * LL + t) * HH + j0 + jl] = h;             // scattered 4B
            if (t + 1 < LL)
                pf4 = *(const float4*)(pre + preoff + (long)(t + 1) * G4);
        }
        __syncthreads();
        if (tid == 0) st_rel(myflag, (unsigned)(t + 1));
    }
}

// ---------------- blocked cumsum: P[b][t][d] = sum_{s<=t} hout[b][s][d] ----------------
__global__ void k_csum1() {      // grid (16, BB): chunk c covers t in [c*64, c*64+64)
    int c = blockIdx.x, b = blockIdx.y;
    int d = threadIdx.x;
    const float* s0 = g_hout + ((long)b * LL + c * 64) * HH + d;
    const float* s1 = s0 + 256;
    float* d0 = g_P + ((long)b * LL + c * 64) * HH + d;
    float* d1 = d0 + 256;
    float a0 = 0.f, a1 = 0.f;
#pragma unroll 8
    for (int t = 0; t < 64; t++) {
        a0 += s0[t * HH]; d0[t * HH] = a0;
        a1 += s1[t * HH]; d1[t * HH] = a1;
    }
    g_csum[((long)b * 16 + c) * HH + d]       = a0;
    g_csum[((long)b * 16 + c) * HH + d + 256] = a1;
}

__global__ void k_csum2() {      // grid (15, BB): chunks 1..15 add exclusive offsets
    int c = blockIdx.x + 1, b = blockIdx.y;
    int d = threadIdx.x;
    float o0 = 0.f, o1 = 0.f;
    for (int cc = 0; cc < c; cc++) {
        o0 += g_csum[((long)b * 16 + cc) * HH + d];
        o1 += g_csum[((long)b * 16 + cc) * HH + d + 256];
    }
    float* d0 = g_P + ((long)b * LL + c * 64) * HH + d;
    float* d1 = d0 + 256;
#pragma unroll 8
    for (int t = 0; t < 64; t++) {
        d0[t * HH] += o0;
        d1[t * HH] += o1;
    }
}

// ---------------- banded online-softmax attention ----------------
__device__ __forceinline__ void upd(float& m, float& l, float4* acc, float sc, const float4* ov) {
    if (sc <= m) {
        float e = __expf(sc - m);
        l += e;
#pragma unroll
        for (int j = 0; j < 4; j++) {
            acc[j].x += e * ov[j].x; acc[j].y += e * ov[j].y;
            acc[j].z += e * ov[j].z; acc[j].w += e * ov[j].w;
        }
    } else {
        float coef = __expf(m - sc);
        l = l * coef + 1.0f;
#pragma unroll
        for (int j = 0; j < 4; j++) {
            acc[j].x = acc[j].x * coef + ov[j].x; acc[j].y = acc[j].y * coef + ov[j].y;
            acc[j].z = acc[j].z * coef + ov[j].z; acc[j].w = acc[j].w * coef + ov[j].w;
        }
        m = sc;
    }
}

__global__ void k_attn() {
    int warp = (blockIdx.x * blockDim.x + threadIdx.x) >> 5;  // 0..16383
    int lane = threadIdx.x & 31;
    int b  = warp >> 9;
    int tp = warp & 511;
    int t0 = tp * 2, t1 = t0 + 1;

    const float* mb = g_mlp  + (long)b * LL * DD;
    const float* ob = g_hout + (long)b * LL * HH;

    float4 q0[4], q1[4], acc0[4], acc1[4];
#pragma unroll
    for (int j = 0; j < 4; j++) {
        q0[j] = *(const float4*)(mb + (long)t0 * DD + lane * 4 + j * 128);
        q1[j] = *(const float4*)(mb + (long)t1 * DD + lane * 4 + j * 128);
        acc0[j] = make_float4(0.f, 0.f, 0.f, 0.f);
        acc1[j] = make_float4(0.f, 0.f, 0.f, 0.f);
    }
    float m0 = -1e30f, m1 = -1e30f, l0 = 0.0f, l1 = 0.0f;

    int slo = t0 - (WIN - 1); if (slo < 0) slo = 0;
    for (int s = slo; s <= t1; s++) {
        float4 ov[4];
        const float* op = ob + (long)s * HH + lane * 4;
#pragma unroll
        for (int j = 0; j < 4; j++) ov[j] = *(const float4*)(op + j * 128);
        float d0 = 0.f, d1 = 0.f;
#pragma unroll
        for (int j = 0; j < 4; j++) {
            d0 += q0[j].x * ov[j].x + q0[j].y * ov[j].y + q0[j].z * ov[j].z + q0[j].w * ov[j].w;
            d1 += q1[j].x * ov[j].x + q1[j].y * ov[j].y + q1[j].z * ov[j].z + q1[j].w * ov[j].w;
        }
#pragma unroll
        for (int off = 16; off; off >>= 1) {
            d0 += __shfl_xor_sync(0xFFFFFFFFu, d0, off);
            d1 += __shfl_xor_sync(0xFFFFFFFFu, d1, off);
        }
        if (s <= t0) {
            float sc = d0 * __expf(-0.6f * (float)(t0 - s));
            upd(m0, l0, acc0, sc, ov);
        }
        if (s >= t1 - (WIN - 1)) {
            float sc = d1 * __expf(-0.6f * (float)(t1 - s));
            upd(m1, l1, acc1, sc, ov);
        }
    }
    // tails: all s <= t-WIN contribute exactly exp(-m) each (fp32-exact vs reference)
    if (t0 >= WIN) {
        float cnt = (float)(t0 - (WIN - 1));
        const float* pp = g_P + ((long)b * LL + (t0 - WIN)) * HH + lane * 4;
        float4 pv[4];
#pragma unroll
        for (int j = 0; j < 4; j++) pv[j] = *(const float4*)(pp + j * 128);
        if (0.0f <= m0) {
            float e = __expf(-m0);
            l0 += cnt * e;
#pragma unroll
            for (int j = 0; j < 4; j++) {
                acc0[j].x += e * pv[j].x; acc0[j].y += e * pv[j].y;
                acc0[j].z += e * pv[j].z; acc0[j].w += e * pv[j].w;
            }
        } else {
            float coef = __expf(m0);
            l0 = l0 * coef + cnt;
#pragma unroll
            for (int j = 0; j < 4; j++) {
                acc0[j].x = acc0[j].x * coef + pv[j].x; acc0[j].y = acc0[j].y * coef + pv[j].y;
                acc0[j].z = acc0[j].z * coef + pv[j].z; acc0[j].w = acc0[j].w * coef + pv[j].w;
            }
            m0 = 0.0f;
        }
    }
    if (t1 >= WIN) {
        float cnt = (float)(t1 - (WIN - 1));
        const float* pp = g_P + ((long)b * LL + (t1 - WIN)) * HH + lane * 4;
        float4 pv[4];
#pragma unroll
        for (int j = 0; j < 4; j++) pv[j] = *(const float4*)(pp + j * 128);
        if (0.0f <= m1) {
            float e = __expf(-m1);
            l1 += cnt * e;
#pragma unroll
            for (int j = 0; j < 4; j++) {
                acc1[j].x += e * pv[j].x; acc1[j].y += e * pv[j].y;
                acc1[j].z += e * pv[j].z; acc1[j].w += e * pv[j].w;
            }
        } else {
            float coef = __expf(m1);
            l1 = l1 * coef + cnt;
#pragma unroll
            for (int j = 0; j < 4; j++) {
                acc1[j].x = acc1[j].x * coef + pv[j].x; acc1[j].y = acc1[j].y * coef + pv[j].y;
                acc1[j].z = acc1[j].z * coef + pv[j].z; acc1[j].w = acc1[j].w * coef + pv[j].w;
            }
            m1 = 0.0f;
        }
    }

    float inv0 = 1.0f / l0, inv1 = 1.0f / l1;
    float* w0 = g_wgt + ((long)b * LL + t0) * HH + lane * 4;
    float* w1 = g_wgt + ((long)b * LL + t1) * HH + lane * 4;
#pragma unroll
    for (int j = 0; j < 4; j++) {
        float4 r0 = make_float4(acc0[j].x * inv0, acc0[j].y * inv0, acc0[j].z * inv0, acc0[j].w * inv0);
        float4 r1 = make_float4(acc1[j].x * inv1, acc1[j].y * inv1, acc1[j].z * inv1, acc1[j].w * inv1);
        *(float4*)(w0 + j * 128) = r0;
        *(float4*)(w1 + j * 128) = r1;
    }
}

// ---------------- launch ----------------
extern "C" void kernel_launch(void* const* d_in, const int* in_sizes, int n_in,
                              void* d_out, int out_size) {
    const float* x        = (const float*)d_in[0];
    const int*   concepts = (const int*)  d_in[1];
    const float* emb      = (const float*)d_in[2];
    const float* Wih      = (const float*)d_in[3];
    const float* Whh      = (const float*)d_in[4];
    const float* bih      = (const float*)d_in[5];
    const float* bhh      = (const float*)d_in[6];
    const float* Wm       = (const float*)d_in[7];
    const float* bm       = (const float*)d_in[8];
    const float* W1       = (const float*)d_in[9];
    const float* b1       = (const float*)d_in[10];
    const float* W2       = (const float*)d_in[11];
    const float* b2       = (const float*)d_in[12];
    float* out = (float*)d_out;

    float *p_pre, *p_cpart, *p_mlp, *p_wgt, *p_h1;
    cudaGetSymbolAddress((void**)&p_pre,   g_pre);
    cudaGetSymbolAddress((void**)&p_cpart, g_cpart);
    cudaGetSymbolAddress((void**)&p_mlp,   g_mlp);
    cudaGetSymbolAddress((void**)&p_wgt,   g_wgt);
    cudaGetSymbolAddress((void**)&p_h1,    g_h1);

    // smem: w_t 32KB + h_s 64KB + ps 32KB + c_s 512B = ~128.5KB
    const int lstm_smem = (512 * 16 + 512 * 32 + 16 * 512 + 128) * 4;
    cudaFuncSetAttribute(k_lstm, cudaFuncAttributeMaxDynamicSharedMemorySize, lstm_smem);

    const int M = BB * LL;   // 32768

    k_init<<<128, 256>>>();
    k_cpart<<<BB * 8, 256>>>(emb, concepts, Wih, bih, bhh);
    // pre = x @ WihA^T + cpart (PERMUTED output: [b][t][j*4+gate])
    k_gemm<false, true><<<dim3(G4 / 128, M / 128), 256>>>(x, DD, Wih, 2 * DD, nullptr, p_cpart,
                                                          p_pre, G4, G4, DD);
    // mlp = x @ Wm^T + bm
    k_gemm<false, false><<<dim3(DD / 128, M / 128), 256>>>(x, DD, Wm, DD, bm, nullptr,
                                                           p_mlp, DD, DD, DD);
    // LSTM recurrence
    k_lstm<<<NCTA_LSTM, 256, lstm_smem>>>(p_pre, Whh);
    // blocked prefix sums of h over time
    k_csum1<<<dim3(16, BB), 256>>>();
    k_csum2<<<dim3(15, BB), 256>>>();
    // attention
    k_attn<<<2048, 256>>>();
    // h1 = relu(weighted @ W1^T + b1)
    k_gemm<true, false><<<dim3(FF / 128, M / 128), 256>>>(p_wgt, HH, W1, HH, b1, nullptr,
                                                          p_h1, FF, FF, HH);
    // res = h1 @ W2^T + b2
    k_gemm<false, false><<<dim3(1, M / 128), 256>>>(p_h1, FF, W2, FF, b2, nullptr,
                                                    out, OUTD, OUTD, FF);
}